// round 13
// baseline (speedup 1.0000x reference)
#include <cuda_runtime.h>
#include <cuda_fp16.h>
#include <math.h>

// ---------------- problem constants ----------------
#define N_USER 50000
#define N_REPO 100000
#define NE     1000000
#define NEP    200000
#define D_IN   256
#define D_EMB  125
#define D_HID  96
#define D_OUT  64

// ---------------- scratch (device globals) ----------------
__device__ __align__(16) __half g_a_user[N_USER * D_IN];
__device__ __align__(16) __half g_a_repo[N_REPO * D_IN];
__device__ __align__(16) __half g_feat_u[N_USER * D_HID];
__device__ __align__(16) __half g_feat_r[N_REPO * D_HID];
__device__ float  g_raw_u [N_USER * D_HID];
__device__ float  g_raw_r [N_REPO * D_HID];
__device__ __align__(16) __half g_out_user[N_USER * D_HID];
__device__ __align__(16) __half g_out_repo[N_REPO * D_HID];
__device__ float  g_new_user[N_USER * D_OUT];
__device__ float  g_new_repo[N_REPO * D_OUT];

__device__ int   g_cnt_u_out[N_USER];
__device__ int   g_cnt_u_in [N_USER];
__device__ int   g_cnt_r_out[N_REPO];
__device__ int   g_cnt_r_in [N_REPO];
__device__ float g_rs_u_out[N_USER], g_rs_u_in[N_USER];
__device__ float g_rs_r_out[N_REPO], g_rs_r_in[N_REPO];

__device__ int g_rowptr_ur[N_REPO + 1];
__device__ int g_rowptr_ru[N_USER + 1];
__device__ int g_cursor_ur[N_REPO];
__device__ int g_cursor_ru[N_USER];
__device__ int g_col_ur[NE];
__device__ int g_col_ru[NE];
__device__ int g_part[128];

__device__ float g_invn_u[N_USER];
__device__ float g_invn_r[N_REPO];

__device__ __align__(16) __half g_WCt_u1[192 * D_IN];
__device__ __align__(16) __half g_WCt_r1[192 * D_IN];
__device__ float g_bc_u1[192];
__device__ float g_bc_r1[192];
__device__ __align__(16) __half g_wc2t_u[128 * D_HID];
__device__ __align__(16) __half g_wc2t_r[128 * D_HID];

// ---------------- preprocessing kernels ----------------
__global__ void k_pack2(const float* __restrict__ W_out_ur, const float* __restrict__ W_ocu,
                        const float* __restrict__ W_out_ru, const float* __restrict__ W_ocr) {
    int i = blockIdx.x * blockDim.x + threadIdx.x;
    if (i >= 2 * 128 * 96) return;
    int half_sel = i / (128 * 96);
    int j = i - half_sel * (128 * 96);
    int n = j / 96, k = j % 96;
    const float* Wa = half_sel ? W_out_ru : W_out_ur;
    const float* Wb = half_sel ? W_ocr    : W_ocu;
    float v = (n < 64) ? Wa[k * 64 + n] : Wb[k * 64 + (n - 64)];
    __half* dst = half_sel ? g_wc2t_r : g_wc2t_u;
    dst[n * 96 + k] = __float2half_rn(v);
}

__global__ void k_fold(const float* __restrict__ W_ue, const float* __restrict__ b_ue,
                       const float* __restrict__ W_hid_ur, const float* __restrict__ W_hcu,
                       const float* __restrict__ W_re, const float* __restrict__ b_re,
                       const float* __restrict__ W_hid_ru, const float* __restrict__ W_hcr) {
    const int PER = D_IN * 192;
    int i = blockIdx.x * blockDim.x + threadIdx.x;
    if (i < 2 * PER) {
        const float* We = (i < PER) ? W_ue : W_re;
        const float* Wm = (i < PER) ? W_hid_ur : W_hid_ru;
        const float* Wr = (i < PER) ? W_hcu : W_hcr;
        __half* WCt = (i < PER) ? g_WCt_u1 : g_WCt_r1;
        int j = (i < PER) ? i : i - PER;
        int n = j / D_IN, m = j % D_IN;
        const float* Wx = (n < 96) ? (Wm + n) : (Wr + n - 96);
        float a = 0.f;
        #pragma unroll 5
        for (int k = 0; k < D_EMB; k++) a += We[m * D_EMB + k] * Wx[k * 96];
        WCt[n * D_IN + m] = __float2half_rn(a);
        return;
    }
    i -= 2 * PER;
    if (i < 384) {
        const float* be = (i < 192) ? b_ue : b_re;
        const float* Wm = (i < 192) ? W_hid_ur : W_hid_ru;
        const float* Wr = (i < 192) ? W_hcu : W_hcr;
        float* bc = (i < 192) ? g_bc_u1 : g_bc_r1;
        int n = i % 192;
        const float* Wx = (n < 96) ? (Wm + n) : (Wr + n - 96);
        float a = 0.f;
        for (int k = 0; k < D_EMB; k++) a += be[k] * Wx[k * 96];
        bc[n] = a;
    }
}

// fp32 -> fp16: 8 floats per thread (2x LDG.128 -> 1x STG.128)
#define NU8 (N_USER * (D_IN / 8))
#define NR8 (N_REPO * (D_IN / 8))
__global__ void k_tofp16(const float* __restrict__ u, const float* __restrict__ r) {
    long i = blockIdx.x * (long)blockDim.x + threadIdx.x;
    const float4* src;
    uint4* dst;
    long j;
    if (i < NU8) { src = (const float4*)u; dst = (uint4*)g_a_user; j = i; }
    else if (i < NU8 + NR8) { src = (const float4*)r; dst = (uint4*)g_a_repo; j = i - NU8; }
    else return;
    float4 v0 = src[2 * j];
    float4 v1 = src[2 * j + 1];
    union { __half2 h[4]; uint4 q; } cv;
    cv.h[0] = __floats2half2_rn(v0.x, v0.y);
    cv.h[1] = __floats2half2_rn(v0.z, v0.w);
    cv.h[2] = __floats2half2_rn(v1.x, v1.y);
    cv.h[3] = __floats2half2_rn(v1.z, v1.w);
    dst[j] = cv.q;
}

__global__ void k_count_all(const int* __restrict__ ur_src, const int* __restrict__ ur_dst,
                            const int* __restrict__ ru_src, const int* __restrict__ ru_dst) {
    int i = blockIdx.x * blockDim.x + threadIdx.x;
    if (i < NE) {
        atomicAdd(&g_cnt_u_out[ur_src[i]], 1);
        atomicAdd(&g_cnt_r_in[ur_dst[i]], 1);
    } else if (i < 2 * NE) {
        int j = i - NE;
        atomicAdd(&g_cnt_r_out[ru_src[j]], 1);
        atomicAdd(&g_cnt_u_in[ru_dst[j]], 1);
    }
}

__global__ void k_rsqrt_all() {
    int i = blockIdx.x * blockDim.x + threadIdx.x;
    if (i < N_USER) { g_rs_u_out[i] = rsqrtf(fmaxf((float)g_cnt_u_out[i], 1.f)); return; }
    i -= N_USER;
    if (i < N_USER) { g_rs_u_in[i] = rsqrtf(fmaxf((float)g_cnt_u_in[i], 1.f)); return; }
    i -= N_USER;
    if (i < N_REPO) { g_rs_r_out[i] = rsqrtf(fmaxf((float)g_cnt_r_out[i], 1.f)); return; }
    i -= N_REPO;
    if (i < N_REPO) { g_rs_r_in[i] = rsqrtf(fmaxf((float)g_cnt_r_in[i], 1.f)); return; }
}

__global__ void k_scan_block(const int* __restrict__ cnt, int* rowptr, int* partial, int n) {
    __shared__ int sh[1024];
    int b = blockIdx.x, t = threadIdx.x;
    int i = b * 1024 + t;
    int v = (i < n) ? cnt[i] : 0;
    sh[t] = v;
    __syncthreads();
    for (int off = 1; off < 1024; off <<= 1) {
        int x = (t >= off) ? sh[t - off] : 0;
        __syncthreads();
        sh[t] += x;
        __syncthreads();
    }
    if (i < n) rowptr[i + 1] = sh[t];
    if (t == 1023) partial[b] = sh[1023];
}

__global__ void k_scan_part(int* partial, int nb) {
    __shared__ int sh[128];
    int t = threadIdx.x;
    int v = (t < nb) ? partial[t] : 0;
    sh[t] = v;
    __syncthreads();
    for (int off = 1; off < 128; off <<= 1) {
        int x = (t >= off) ? sh[t - off] : 0;
        __syncthreads();
        sh[t] += x;
        __syncthreads();
    }
    if (t < nb) partial[t] = sh[t] - v;
}

__global__ void k_scan_add(int* rowptr, int* cursor, const int* __restrict__ partial, int n) {
    int i = blockIdx.x * blockDim.x + threadIdx.x;
    if (i == 0) { rowptr[0] = 0; cursor[0] = 0; }
    if (i < n) {
        int v = rowptr[i + 1] + partial[i >> 10];
        rowptr[i + 1] = v;
        if (i + 1 < n) cursor[i + 1] = v;
    }
}

__global__ void k_fill_all(const int* __restrict__ ur_src, const int* __restrict__ ur_dst,
                           const int* __restrict__ ru_src, const int* __restrict__ ru_dst) {
    int i = blockIdx.x * blockDim.x + threadIdx.x;
    if (i < NE) {
        int p = atomicAdd(&g_cursor_ur[ur_dst[i]], 1);
        g_col_ur[p] = ur_src[i];
    } else if (i < 2 * NE) {
        int j = i - NE;
        int p = atomicAdd(&g_cursor_ru[ru_dst[j]], 1);
        g_col_ru[p] = ru_src[j];
    }
}

// ---------------- fp16 GEMM: cp.async double-buffer + ldmatrix + m16n8k16 ----------------
// 256 threads, 8 warps (4m x 2n), warp tile 32x32 -> 32 acc regs -> higher occupancy
#define BM 128
#define BN 64
#define BK 32
#define APITCH 40
#define BPITCH 40
#define AHALVES (BM * APITCH)
#define BHALVES (BN * BPITCH)

__device__ __forceinline__ void mma_f16(float c[4],
                                        unsigned a0, unsigned a1, unsigned a2, unsigned a3,
                                        unsigned b0, unsigned b1) {
    asm volatile(
        "mma.sync.aligned.m16n8k16.row.col.f32.f16.f16.f32 "
        "{%0,%1,%2,%3}, {%4,%5,%6,%7}, {%8,%9}, {%0,%1,%2,%3};"
        : "+f"(c[0]), "+f"(c[1]), "+f"(c[2]), "+f"(c[3])
        : "r"(a0), "r"(a1), "r"(a2), "r"(a3), "r"(b0), "r"(b1));
}

__device__ __forceinline__ void ldsm_x4(unsigned& r0, unsigned& r1, unsigned& r2, unsigned& r3,
                                        unsigned addr) {
    asm volatile("ldmatrix.sync.aligned.m8n8.x4.shared.b16 {%0,%1,%2,%3}, [%4];"
                 : "=r"(r0), "=r"(r1), "=r"(r2), "=r"(r3) : "r"(addr));
}

__device__ __forceinline__ void cp_async16(unsigned dst, const void* src) {
    asm volatile("cp.async.cg.shared.global [%0], [%1], 16;" :: "r"(dst), "l"(src));
}
__device__ __forceinline__ void cp_commit() {
    asm volatile("cp.async.commit_group;");
}
__device__ __forceinline__ void cp_wait_all() {
    asm volatile("cp.async.wait_group 0;");
}

__global__ __launch_bounds__(256) void k_gemm_f16(
    const __half* __restrict__ A, const __half* __restrict__ Wt,
    __half* __restrict__ C1h, int ld1,
    float* __restrict__ C2, int ld2, int nsplit,
    int M, int N, int K,
    const float* __restrict__ bias)
{
    __shared__ __half As_s[2][AHALVES];
    __shared__ __half Bs_s[2][BHALVES];

    const int tid = threadIdx.x;
    const int warp = tid >> 5, lane = tid & 31;
    const int wm = (warp >> 1) * 32;   // 4 warp rows of 32
    const int wn = (warp & 1) * 32;    // 2 warp cols of 32
    const int m0 = blockIdx.y * BM;
    const int n0 = blockIdx.x * BN;
    const int r = lane >> 2, kc = lane & 3;

    float acc[2][4][4];
    #pragma unroll
    for (int a = 0; a < 2; a++)
        #pragma unroll
        for (int b = 0; b < 4; b++)
            #pragma unroll
            for (int c = 0; c < 4; c++) acc[a][b][c] = 0.f;

    const unsigned as0 = (unsigned)__cvta_generic_to_shared(&As_s[0][0]);
    const unsigned bs0 = (unsigned)__cvta_generic_to_shared(&Bs_s[0][0]);

    const int q = lane >> 3, lr = lane & 7;
    const unsigned a_lm = ((wm + (q & 1) * 8 + lr) * APITCH + (q >> 1) * 8) << 1;
    const unsigned b_lm = ((wn + (q >> 1) * 8 + lr) * BPITCH + (q & 1) * 8) << 1;

    // staging: 256 threads; A 128 rows x 4 chunks (2 reps), B 64 rows x 4 chunks (1 rep)
    const int a_row = tid >> 2, a_c = tid & 3;

    const int T = K / BK;

    {
        const int k0 = 0;
        #pragma unroll
        for (int j = 0; j < 2; j++) {
            int row = a_row + j * 64;
            int m = m0 + row;
            if (m < M)
                cp_async16(as0 + ((row * APITCH + a_c * 8) << 1),
                           A + (size_t)m * K + k0 + a_c * 8);
        }
        cp_async16(bs0 + ((a_row * BPITCH + a_c * 8) << 1),
                   Wt + (size_t)(n0 + a_row) * K + k0 + a_c * 8);
        cp_commit();
    }

    for (int t = 0; t < T; t++) {
        cp_wait_all();
        __syncthreads();

        if (t + 1 < T) {
            const int k0 = (t + 1) * BK;
            const unsigned ab = as0 + ((t + 1) & 1) * (AHALVES * 2);
            const unsigned bb = bs0 + ((t + 1) & 1) * (BHALVES * 2);
            #pragma unroll
            for (int j = 0; j < 2; j++) {
                int row = a_row + j * 64;
                int m = m0 + row;
                if (m < M)
                    cp_async16(ab + ((row * APITCH + a_c * 8) << 1),
                               A + (size_t)m * K + k0 + a_c * 8);
            }
            cp_async16(bb + ((a_row * BPITCH + a_c * 8) << 1),
                       Wt + (size_t)(n0 + a_row) * K + k0 + a_c * 8);
            cp_commit();
        }

        const unsigned abuf = as0 + (t & 1) * (AHALVES * 2) + a_lm;
        const unsigned bbuf = bs0 + (t & 1) * (BHALVES * 2) + b_lm;
        #pragma unroll
        for (int g = 0; g < 2; g++) {
            unsigned af[2][4], bf[4][2];
            #pragma unroll
            for (int mt = 0; mt < 2; mt++)
                ldsm_x4(af[mt][0], af[mt][1], af[mt][2], af[mt][3],
                        abuf + ((mt * 16 * APITCH + g * 16) << 1));
            #pragma unroll
            for (int np = 0; np < 2; np++) {
                unsigned r0, r1, r2, r3;
                ldsm_x4(r0, r1, r2, r3, bbuf + ((np * 16 * BPITCH + g * 16) << 1));
                bf[2 * np][0] = r0;  bf[2 * np][1] = r1;
                bf[2 * np + 1][0] = r2;  bf[2 * np + 1][1] = r3;
            }
            #pragma unroll
            for (int mt = 0; mt < 2; mt++)
                #pragma unroll
                for (int nt = 0; nt < 4; nt++)
                    mma_f16(acc[mt][nt], af[mt][0], af[mt][1], af[mt][2], af[mt][3],
                            bf[nt][0], bf[nt][1]);
        }
        __syncthreads();
    }

    #pragma unroll
    for (int mt = 0; mt < 2; mt++) {
        #pragma unroll
        for (int i2 = 0; i2 < 2; i2++) {
            int m = m0 + wm + mt * 16 + r + i2 * 8;
            if (m >= M) continue;
            #pragma unroll
            for (int nt = 0; nt < 4; nt++) {
                int n = n0 + wn + nt * 8 + kc * 2;
                float v0 = acc[mt][nt][i2 * 2 + 0];
                float v1 = acc[mt][nt][i2 * 2 + 1];
                if (bias) { v0 += bias[n]; v1 += bias[n + 1]; }
                if (n < nsplit) {
                    __half2 h = __floats2half2_rn(v0, v1);
                    *(__half2*)(C1h + (size_t)m * ld1 + n) = h;
                } else {
                    *(float2*)(C2 + (size_t)m * ld2 + n - nsplit) = make_float2(v0, v1);
                }
            }
        }
    }
}

// ---------------- fused SpMM + residual epilogue (layer 1: fp16 out) ----------------
__global__ void k_spmm_out96(const __half* __restrict__ feat, const int* __restrict__ rowptr,
                             const int* __restrict__ col, const float* __restrict__ rs_src,
                             const float* __restrict__ raw, const float* __restrict__ rs_in,
                             const float* __restrict__ b1, const float* __restrict__ b2,
                             __half* __restrict__ out, int n_rows) {
    int w = (blockIdx.x * blockDim.x + threadIdx.x) >> 5;
    int lane = threadIdx.x & 31;
    if (w >= n_rows) return;
    int s = rowptr[w], e = rowptr[w + 1];
    bool act = lane < 24;
    int d = lane * 4;
    float4 a0 = make_float4(0.f, 0.f, 0.f, 0.f);
    float4 a1 = make_float4(0.f, 0.f, 0.f, 0.f);
    int i = s;
    for (; i + 3 < e; i += 4) {
        int c0 = col[i], c1 = col[i + 1], c2 = col[i + 2], c3 = col[i + 3];
        float s0 = rs_src[c0], s1 = rs_src[c1], s2 = rs_src[c2], s3 = rs_src[c3];
        if (act) {
            uint2 q0 = *(const uint2*)(feat + (size_t)c0 * 96 + d);
            uint2 q1 = *(const uint2*)(feat + (size_t)c1 * 96 + d);
            uint2 q2 = *(const uint2*)(feat + (size_t)c2 * 96 + d);
            uint2 q3 = *(const uint2*)(feat + (size_t)c3 * 96 + d);
            float2 f;
            f = __half22float2(*(__half2*)&q0.x); a0.x += f.x * s0; a0.y += f.y * s0;
            f = __half22float2(*(__half2*)&q0.y); a0.z += f.x * s0; a0.w += f.y * s0;
            f = __half22float2(*(__half2*)&q1.x); a1.x += f.x * s1; a1.y += f.y * s1;
            f = __half22float2(*(__half2*)&q1.y); a1.z += f.x * s1; a1.w += f.y * s1;
            f = __half22float2(*(__half2*)&q2.x); a0.x += f.x * s2; a0.y += f.y * s2;
            f = __half22float2(*(__half2*)&q2.y); a0.z += f.x * s2; a0.w += f.y * s2;
            f = __half22float2(*(__half2*)&q3.x); a1.x += f.x * s3; a1.y += f.y * s3;
            f = __half22float2(*(__half2*)&q3.y); a1.z += f.x * s3; a1.w += f.y * s3;
        }
    }
    for (; i < e; i++) {
        int c0 = col[i];
        float s0 = rs_src[c0];
        if (act) {
            uint2 q0 = *(const uint2*)(feat + (size_t)c0 * 96 + d);
            float2 f;
            f = __half22float2(*(__half2*)&q0.x); a0.x += f.x * s0; a0.y += f.y * s0;
            f = __half22float2(*(__half2*)&q0.y); a0.z += f.x * s0; a0.w += f.y * s0;
        }
    }
    if (act) {
        float sc = rs_in[w];
        float4 r4 = *(const float4*)(raw + (size_t)w * 96 + d);
        float ox = fmaxf(r4.x + b1[d + 0] + b2[d + 0] + (a0.x + a1.x) * sc, 0.f);
        float oy = fmaxf(r4.y + b1[d + 1] + b2[d + 1] + (a0.y + a1.y) * sc, 0.f);
        float oz = fmaxf(r4.z + b1[d + 2] + b2[d + 2] + (a0.z + a1.z) * sc, 0.f);
        float ow = fmaxf(r4.w + b1[d + 3] + b2[d + 3] + (a0.w + a1.w) * sc, 0.f);
        union { __half2 h[2]; uint2 q; } cv;
        cv.h[0] = __floats2half2_rn(ox, oy);
        cv.h[1] = __floats2half2_rn(oz, ow);
        *(uint2*)(out + (size_t)w * 96 + d) = cv.q;
    }
}

// layer 2 (D=64): HALF-WARP per row (16 lanes), fp32 out + fused inverse-norm
__global__ void k_spmm_out64_norm(const __half* __restrict__ feat, const int* __restrict__ rowptr,
                                  const int* __restrict__ col, const float* __restrict__ rs_src,
                                  const float* __restrict__ raw, const float* __restrict__ rs_in,
                                  const float* __restrict__ b1, const float* __restrict__ b2,
                                  float* __restrict__ out, float* __restrict__ invn, int n_rows) {
    int gt = blockIdx.x * blockDim.x + threadIdx.x;
    int w = gt >> 4;
    int lane = threadIdx.x & 15;
    if (w >= n_rows) return;
    int s = rowptr[w], e = rowptr[w + 1];
    int d = lane * 4;
    float4 a0 = make_float4(0.f, 0.f, 0.f, 0.f);
    float4 a1 = make_float4(0.f, 0.f, 0.f, 0.f);
    int i = s;
    for (; i + 3 < e; i += 4) {
        int c0 = col[i], c1 = col[i + 1], c2 = col[i + 2], c3 = col[i + 3];
        float s0 = rs_src[c0], s1 = rs_src[c1], s2 = rs_src[c2], s3 = rs_src[c3];
        uint2 q0 = *(const uint2*)(feat + (size_t)c0 * 64 + d);
        uint2 q1 = *(const uint2*)(feat + (size_t)c1 * 64 + d);
        uint2 q2 = *(const uint2*)(feat + (size_t)c2 * 64 + d);
        uint2 q3 = *(const uint2*)(feat + (size_t)c3 * 64 + d);
        float2 f;
        f = __half22float2(*(__half2*)&q0.x); a0.x += f.x * s0; a0.y += f.y * s0;
        f = __half22float2(*(__half2*)&q0.y); a0.z += f.x * s0; a0.w += f.y * s0;
        f = __half22float2(*(__half2*)&q1.x); a1.x += f.x * s1; a1.y += f.y * s1;
        f = __half22float2(*(__half2*)&q1.y); a1.z += f.x * s1; a1.w += f.y * s1;
        f = __half22float2(*(__half2*)&q2.x); a0.x += f.x * s2; a0.y += f.y * s2;
        f = __half22float2(*(__half2*)&q2.y); a0.z += f.x * s2; a0.w += f.y * s2;
        f = __half22float2(*(__half2*)&q3.x); a1.x += f.x * s3; a1.y += f.y * s3;
        f = __half22float2(*(__half2*)&q3.y); a1.z += f.x * s3; a1.w += f.y * s3;
    }
    for (; i < e; i++) {
        int c0 = col[i];
        float s0 = rs_src[c0];
        uint2 q0 = *(const uint2*)(feat + (size_t)c0 * 64 + d);
        float2 f;
        f = __half22float2(*(__half2*)&q0.x); a0.x += f.x * s0; a0.y += f.y * s0;
        f = __half22float2(*(__half2*)&q0.y); a0.z += f.x * s0; a0.w += f.y * s0;
    }
    float sq;
    {
        float sc = rs_in[w];
        float4 r4 = *(const float4*)(raw + (size_t)w * 64 + d);
        float4 o;
        o.x = fmaxf(r4.x + b1[d + 0] + b2[d + 0] + (a0.x + a1.x) * sc, 0.f);
        o.y = fmaxf(r4.y + b1[d + 1] + b2[d + 1] + (a0.y + a1.y) * sc, 0.f);
        o.z = fmaxf(r4.z + b1[d + 2] + b2[d + 2] + (a0.z + a1.z) * sc, 0.f);
        o.w = fmaxf(r4.w + b1[d + 3] + b2[d + 3] + (a0.w + a1.w) * sc, 0.f);
        *(float4*)(out + (size_t)w * 64 + d) = o;
        sq = o.x * o.x + o.y * o.y + o.z * o.z + o.w * o.w;
    }
    #pragma unroll
    for (int off = 8; off; off >>= 1) sq += __shfl_xor_sync(0xffffffffu, sq, off);
    if (lane == 0) invn[w] = 1.0f / fmaxf(sqrtf(sq), 1e-12f);
}

// ---------------- score ----------------
__global__ void k_score_all(const float* __restrict__ hu, const float* __restrict__ hr,
                            const float* __restrict__ invn_u, const float* __restrict__ invn_r,
                            const int* __restrict__ pos_u, const int* __restrict__ pos_r,
                            const int* __restrict__ neg_u, const int* __restrict__ neg_r,
                            float* __restrict__ out) {
    int w = (blockIdx.x * blockDim.x + threadIdx.x) >> 5;
    int lane = threadIdx.x & 31;
    if (w >= 2 * NEP) return;
    int u, r;
    if (w < NEP) { u = pos_u[w]; r = pos_r[w]; }
    else         { u = neg_u[w - NEP]; r = neg_r[w - NEP]; }
    const float* a = hu + (size_t)u * D_OUT;
    const float* b = hr + (size_t)r * D_OUT;
    float s = a[lane] * b[lane] + a[lane + 32] * b[lane + 32];
    #pragma unroll
    for (int off = 16; off; off >>= 1) s += __shfl_xor_sync(0xffffffffu, s, off);
    if (lane == 0) out[w] = s * invn_u[u] * invn_r[r];
}

// ---------------- host ----------------
static inline void* sym(const void* s) {
    void* p = nullptr;
    cudaGetSymbolAddress(&p, s);
    return p;
}

extern "C" void kernel_launch(void* const* d_in, const int* in_sizes, int n_in,
                              void* d_out, int out_size) {
    const float* user_feat = (const float*)d_in[0];
    const float* repo_feat = (const float*)d_in[1];
    const float* W_ue = (const float*)d_in[2];   const float* b_ue = (const float*)d_in[3];
    const float* W_re = (const float*)d_in[4];   const float* b_re = (const float*)d_in[5];
    const float* W_hid_ur = (const float*)d_in[6];  const float* b_hid_ur = (const float*)d_in[7];
    const float* W_hid_ru = (const float*)d_in[8];  const float* b_hid_ru = (const float*)d_in[9];
    const float* W_out_ur = (const float*)d_in[10]; const float* b_out_ur = (const float*)d_in[11];
    const float* W_out_ru = (const float*)d_in[12]; const float* b_out_ru = (const float*)d_in[13];
    const float* W_hcu = (const float*)d_in[14]; const float* b_hcu = (const float*)d_in[15];
    const float* W_hcr = (const float*)d_in[16]; const float* b_hcr = (const float*)d_in[17];
    const float* W_ocu = (const float*)d_in[18]; const float* b_ocu = (const float*)d_in[19];
    const float* W_ocr = (const float*)d_in[20]; const float* b_ocr = (const float*)d_in[21];
    const int* e_ur_src = (const int*)d_in[22];
    const int* e_ur_dst = (const int*)d_in[23];
    const int* e_ru_src = (const int*)d_in[24];
    const int* e_ru_dst = (const int*)d_in[25];
    const int* pos_u = (const int*)d_in[26];
    const int* pos_r = (const int*)d_in[27];
    const int* neg_u = (const int*)d_in[28];
    const int* neg_r = (const int*)d_in[29];
    float* out = (float*)d_out;

    __half* a_user = (__half*)sym(g_a_user);
    __half* a_repo = (__half*)sym(g_a_repo);
    __half* feat_u = (__half*)sym(g_feat_u);
    __half* feat_r = (__half*)sym(g_feat_r);
    float*  raw_u  = (float*)sym(g_raw_u);
    float*  raw_r  = (float*)sym(g_raw_r);
    __half* out_user = (__half*)sym(g_out_user);
    __half* out_repo = (__half*)sym(g_out_repo);
    float*  new_user = (float*)sym(g_new_user);
    float*  new_repo = (float*)sym(g_new_repo);
    int* cnt_u_out = (int*)sym(g_cnt_u_out);
    int* cnt_u_in  = (int*)sym(g_cnt_u_in);
    int* cnt_r_out = (int*)sym(g_cnt_r_out);
    int* cnt_r_in  = (int*)sym(g_cnt_r_in);
    float* rs_u_out = (float*)sym(g_rs_u_out);
    float* rs_u_in  = (float*)sym(g_rs_u_in);
    float* rs_r_out = (float*)sym(g_rs_r_out);
    float* rs_r_in  = (float*)sym(g_rs_r_in);
    int* rowptr_ur = (int*)sym(g_rowptr_ur);
    int* rowptr_ru = (int*)sym(g_rowptr_ru);
    int* cursor_ur = (int*)sym(g_cursor_ur);
    int* cursor_ru = (int*)sym(g_cursor_ru);
    int* col_ur = (int*)sym(g_col_ur);
    int* col_ru = (int*)sym(g_col_ru);
    int* part   = (int*)sym(g_part);
    float* invn_u = (float*)sym(g_invn_u);
    float* invn_r = (float*)sym(g_invn_r);
    __half* WCt_u1 = (__half*)sym(g_WCt_u1);
    __half* WCt_r1 = (__half*)sym(g_WCt_r1);
    float* bc_u1 = (float*)sym(g_bc_u1);
    float* bc_r1 = (float*)sym(g_bc_r1);
    __half* wc2t_u = (__half*)sym(g_wc2t_u);
    __half* wc2t_r = (__half*)sym(g_wc2t_r);

    const int T = 256;
    auto blocks = [](long n, int t) { return (int)((n + t - 1) / t); };

    cudaMemsetAsync(cnt_u_out, 0, N_USER * sizeof(int), 0);
    cudaMemsetAsync(cnt_u_in,  0, N_USER * sizeof(int), 0);
    cudaMemsetAsync(cnt_r_out, 0, N_REPO * sizeof(int), 0);
    cudaMemsetAsync(cnt_r_in,  0, N_REPO * sizeof(int), 0);

    k_tofp16<<<blocks((long)NU8 + NR8, T), T>>>(user_feat, repo_feat);
    k_pack2<<<blocks(2 * 128 * 96, T), T>>>(W_out_ur, W_ocu, W_out_ru, W_ocr);
    k_fold<<<blocks(2L * D_IN * 192 + 384, T), T>>>(W_ue, b_ue, W_hid_ur, W_hcu,
                                                    W_re, b_re, W_hid_ru, W_hcr);

    dim3 tb(256);
    auto grid = [](int M, int N) { return dim3(N / BN, (M + BM - 1) / BM); };

    // layer-1 fused GEMMs: Xh @ WCt^T + bc -> [feat fp16 | raw fp32]
    k_gemm_f16<<<grid(N_REPO, 192), tb>>>(a_repo, WCt_r1,
        feat_r, D_HID, raw_r, D_HID, D_HID, N_REPO, 192, D_IN, bc_r1);
    k_gemm_f16<<<grid(N_USER, 192), tb>>>(a_user, WCt_u1,
        feat_u, D_HID, raw_u, D_HID, D_HID, N_USER, 192, D_IN, bc_u1);

    // graph structure
    k_count_all<<<blocks(2L * NE, T), T>>>(e_ur_src, e_ur_dst, e_ru_src, e_ru_dst);
    k_rsqrt_all<<<blocks(2L * (N_USER + N_REPO), T), T>>>();
    int nb_r = (N_REPO + 1023) / 1024;
    int nb_u = (N_USER + 1023) / 1024;
    k_scan_block<<<nb_r, 1024>>>(cnt_r_in, rowptr_ur, part, N_REPO);
    k_scan_part<<<1, 128>>>(part, nb_r);
    k_scan_add<<<blocks(N_REPO, T), T>>>(rowptr_ur, cursor_ur, part, N_REPO);
    k_scan_block<<<nb_u, 1024>>>(cnt_u_in, rowptr_ru, part, N_USER);
    k_scan_part<<<1, 128>>>(part, nb_u);
    k_scan_add<<<blocks(N_USER, T), T>>>(rowptr_ru, cursor_ru, part, N_USER);
    k_fill_all<<<blocks(2L * NE, T), T>>>(e_ur_src, e_ur_dst, e_ru_src, e_ru_dst);

    // layer-1 SpMM + residual -> fp16 out
    k_spmm_out96<<<blocks(N_USER * 32L, T), T>>>(feat_r, rowptr_ru, col_ru, rs_r_out,
                                                 raw_u, rs_u_in, b_hcu, b_hid_ru,
                                                 out_user, N_USER);
    k_spmm_out96<<<blocks(N_REPO * 32L, T), T>>>(feat_u, rowptr_ur, col_ur, rs_u_out,
                                                 raw_r, rs_r_in, b_hcr, b_hid_ur,
                                                 out_repo, N_REPO);

    // layer-2 GEMMs (K=96)
    k_gemm_f16<<<grid(N_REPO, 128), tb>>>(out_repo, wc2t_r,
        feat_r, D_OUT, raw_r, D_OUT, D_OUT, N_REPO, 128, D_HID, nullptr);
    k_gemm_f16<<<grid(N_USER, 128), tb>>>(out_user, wc2t_u,
        feat_u, D_OUT, raw_u, D_OUT, D_OUT, N_USER, 128, D_HID, nullptr);

    // layer-2 SpMM + residual + norm (half-warp per row)
    k_spmm_out64_norm<<<blocks(N_USER * 16L, T), T>>>(feat_r, rowptr_ru, col_ru, rs_r_out,
                                                      raw_u, rs_u_in, b_ocu, b_out_ru,
                                                      new_user, invn_u, N_USER);
    k_spmm_out64_norm<<<blocks(N_REPO * 16L, T), T>>>(feat_u, rowptr_ur, col_ur, rs_u_out,
                                                      raw_r, rs_r_in, b_ocr, b_out_ur,
                                                      new_repo, invn_r, N_REPO);

    // cosine scores
    k_score_all<<<blocks(2L * NEP * 32, T), T>>>(new_user, new_repo, invn_u, invn_r,
                                                 pos_u, pos_r, neg_u, neg_r, out);
}

// round 14
// speedup vs baseline: 1.0838x; 1.0838x over previous
#include <cuda_runtime.h>
#include <cuda_fp16.h>
#include <math.h>

// ---------------- problem constants ----------------
#define N_USER 50000
#define N_REPO 100000
#define NE     1000000
#define NEP    200000
#define D_IN   256
#define D_EMB  125
#define D_HID  96
#define D_OUT  64

// ---------------- scratch (device globals) ----------------
__device__ __align__(16) __half g_a_user[N_USER * D_IN];
__device__ __align__(16) __half g_a_repo[N_REPO * D_IN];
__device__ __align__(16) __half g_feat_u[N_USER * D_HID];
__device__ __align__(16) __half g_feat_r[N_REPO * D_HID];
__device__ float  g_raw_u [N_USER * D_HID];
__device__ float  g_raw_r [N_REPO * D_HID];
__device__ __align__(16) __half g_out_user[N_USER * D_HID];
__device__ __align__(16) __half g_out_repo[N_REPO * D_HID];
__device__ float  g_new_user[N_USER * D_OUT];
__device__ float  g_new_repo[N_REPO * D_OUT];

__device__ int   g_cnt_u_out[N_USER];
__device__ int   g_cnt_u_in [N_USER];
__device__ int   g_cnt_r_out[N_REPO];
__device__ int   g_cnt_r_in [N_REPO];
__device__ float g_rs_u_out[N_USER], g_rs_u_in[N_USER];
__device__ float g_rs_r_out[N_REPO], g_rs_r_in[N_REPO];

__device__ int g_rowptr_ur[N_REPO + 1];
__device__ int g_rowptr_ru[N_USER + 1];
__device__ int g_cursor_ur[N_REPO];
__device__ int g_cursor_ru[N_USER];
__device__ int g_col_ur[NE];
__device__ int g_col_ru[NE];
__device__ int g_part[128];

__device__ float g_invn_u[N_USER];
__device__ float g_invn_r[N_REPO];

__device__ __align__(16) __half g_WCt_u1[192 * D_IN];
__device__ __align__(16) __half g_WCt_r1[192 * D_IN];
__device__ float g_bc_u1[192];
__device__ float g_bc_r1[192];
__device__ __align__(16) __half g_wc2t_u[128 * D_HID];
__device__ __align__(16) __half g_wc2t_r[128 * D_HID];

// ---------------- preprocessing kernels ----------------
__global__ void k_pack2(const float* __restrict__ W_out_ur, const float* __restrict__ W_ocu,
                        const float* __restrict__ W_out_ru, const float* __restrict__ W_ocr) {
    int i = blockIdx.x * blockDim.x + threadIdx.x;
    if (i >= 2 * 128 * 96) return;
    int half_sel = i / (128 * 96);
    int j = i - half_sel * (128 * 96);
    int n = j / 96, k = j % 96;
    const float* Wa = half_sel ? W_out_ru : W_out_ur;
    const float* Wb = half_sel ? W_ocr    : W_ocu;
    float v = (n < 64) ? Wa[k * 64 + n] : Wb[k * 64 + (n - 64)];
    __half* dst = half_sel ? g_wc2t_r : g_wc2t_u;
    dst[n * 96 + k] = __float2half_rn(v);
}

__global__ void k_fold(const float* __restrict__ W_ue, const float* __restrict__ b_ue,
                       const float* __restrict__ W_hid_ur, const float* __restrict__ W_hcu,
                       const float* __restrict__ W_re, const float* __restrict__ b_re,
                       const float* __restrict__ W_hid_ru, const float* __restrict__ W_hcr) {
    const int PER = D_IN * 192;
    int i = blockIdx.x * blockDim.x + threadIdx.x;
    if (i < 2 * PER) {
        const float* We = (i < PER) ? W_ue : W_re;
        const float* Wm = (i < PER) ? W_hid_ur : W_hid_ru;
        const float* Wr = (i < PER) ? W_hcu : W_hcr;
        __half* WCt = (i < PER) ? g_WCt_u1 : g_WCt_r1;
        int j = (i < PER) ? i : i - PER;
        int n = j / D_IN, m = j % D_IN;
        const float* Wx = (n < 96) ? (Wm + n) : (Wr + n - 96);
        float a = 0.f;
        #pragma unroll 5
        for (int k = 0; k < D_EMB; k++) a += We[m * D_EMB + k] * Wx[k * 96];
        WCt[n * D_IN + m] = __float2half_rn(a);
        return;
    }
    i -= 2 * PER;
    if (i < 384) {
        const float* be = (i < 192) ? b_ue : b_re;
        const float* Wm = (i < 192) ? W_hid_ur : W_hid_ru;
        const float* Wr = (i < 192) ? W_hcu : W_hcr;
        float* bc = (i < 192) ? g_bc_u1 : g_bc_r1;
        int n = i % 192;
        const float* Wx = (n < 96) ? (Wm + n) : (Wr + n - 96);
        float a = 0.f;
        for (int k = 0; k < D_EMB; k++) a += be[k] * Wx[k * 96];
        bc[n] = a;
    }
}

// fp32 -> fp16: 8 floats per thread (2x LDG.128 -> 1x STG.128)
#define NU8 (N_USER * (D_IN / 8))
#define NR8 (N_REPO * (D_IN / 8))
__global__ void k_tofp16(const float* __restrict__ u, const float* __restrict__ r) {
    long i = blockIdx.x * (long)blockDim.x + threadIdx.x;
    const float4* src;
    uint4* dst;
    long j;
    if (i < NU8) { src = (const float4*)u; dst = (uint4*)g_a_user; j = i; }
    else if (i < NU8 + NR8) { src = (const float4*)r; dst = (uint4*)g_a_repo; j = i - NU8; }
    else return;
    float4 v0 = src[2 * j];
    float4 v1 = src[2 * j + 1];
    union { __half2 h[4]; uint4 q; } cv;
    cv.h[0] = __floats2half2_rn(v0.x, v0.y);
    cv.h[1] = __floats2half2_rn(v0.z, v0.w);
    cv.h[2] = __floats2half2_rn(v1.x, v1.y);
    cv.h[3] = __floats2half2_rn(v1.z, v1.w);
    dst[j] = cv.q;
}

__global__ void k_count_all(const int* __restrict__ ur_src, const int* __restrict__ ur_dst,
                            const int* __restrict__ ru_src, const int* __restrict__ ru_dst) {
    int i = blockIdx.x * blockDim.x + threadIdx.x;
    if (i < NE) {
        atomicAdd(&g_cnt_u_out[ur_src[i]], 1);
        atomicAdd(&g_cnt_r_in[ur_dst[i]], 1);
    } else if (i < 2 * NE) {
        int j = i - NE;
        atomicAdd(&g_cnt_r_out[ru_src[j]], 1);
        atomicAdd(&g_cnt_u_in[ru_dst[j]], 1);
    }
}

__global__ void k_rsqrt_all() {
    int i = blockIdx.x * blockDim.x + threadIdx.x;
    if (i < N_USER) { g_rs_u_out[i] = rsqrtf(fmaxf((float)g_cnt_u_out[i], 1.f)); return; }
    i -= N_USER;
    if (i < N_USER) { g_rs_u_in[i] = rsqrtf(fmaxf((float)g_cnt_u_in[i], 1.f)); return; }
    i -= N_USER;
    if (i < N_REPO) { g_rs_r_out[i] = rsqrtf(fmaxf((float)g_cnt_r_out[i], 1.f)); return; }
    i -= N_REPO;
    if (i < N_REPO) { g_rs_r_in[i] = rsqrtf(fmaxf((float)g_cnt_r_in[i], 1.f)); return; }
}

__global__ void k_scan_block(const int* __restrict__ cnt, int* rowptr, int* partial, int n) {
    __shared__ int sh[1024];
    int b = blockIdx.x, t = threadIdx.x;
    int i = b * 1024 + t;
    int v = (i < n) ? cnt[i] : 0;
    sh[t] = v;
    __syncthreads();
    for (int off = 1; off < 1024; off <<= 1) {
        int x = (t >= off) ? sh[t - off] : 0;
        __syncthreads();
        sh[t] += x;
        __syncthreads();
    }
    if (i < n) rowptr[i + 1] = sh[t];
    if (t == 1023) partial[b] = sh[1023];
}

__global__ void k_scan_part(int* partial, int nb) {
    __shared__ int sh[128];
    int t = threadIdx.x;
    int v = (t < nb) ? partial[t] : 0;
    sh[t] = v;
    __syncthreads();
    for (int off = 1; off < 128; off <<= 1) {
        int x = (t >= off) ? sh[t - off] : 0;
        __syncthreads();
        sh[t] += x;
        __syncthreads();
    }
    if (t < nb) partial[t] = sh[t] - v;
}

__global__ void k_scan_add(int* rowptr, int* cursor, const int* __restrict__ partial, int n) {
    int i = blockIdx.x * blockDim.x + threadIdx.x;
    if (i == 0) { rowptr[0] = 0; cursor[0] = 0; }
    if (i < n) {
        int v = rowptr[i + 1] + partial[i >> 10];
        rowptr[i + 1] = v;
        if (i + 1 < n) cursor[i + 1] = v;
    }
}

__global__ void k_fill_all(const int* __restrict__ ur_src, const int* __restrict__ ur_dst,
                           const int* __restrict__ ru_src, const int* __restrict__ ru_dst) {
    int i = blockIdx.x * blockDim.x + threadIdx.x;
    if (i < NE) {
        int p = atomicAdd(&g_cursor_ur[ur_dst[i]], 1);
        g_col_ur[p] = ur_src[i];
    } else if (i < 2 * NE) {
        int j = i - NE;
        int p = atomicAdd(&g_cursor_ru[ru_dst[j]], 1);
        g_col_ru[p] = ru_src[j];
    }
}

// ---------------- fp16 GEMM: cp.async double-buffer + ldmatrix + m16n8k16 ----------------
// (R12 config: 128 threads, 4 warps 2x2, warp tile 64x32 — measured best)
#define BM 128
#define BN 64
#define BK 32
#define APITCH 40
#define BPITCH 40
#define AHALVES (BM * APITCH)
#define BHALVES (BN * BPITCH)

__device__ __forceinline__ void mma_f16(float c[4],
                                        unsigned a0, unsigned a1, unsigned a2, unsigned a3,
                                        unsigned b0, unsigned b1) {
    asm volatile(
        "mma.sync.aligned.m16n8k16.row.col.f32.f16.f16.f32 "
        "{%0,%1,%2,%3}, {%4,%5,%6,%7}, {%8,%9}, {%0,%1,%2,%3};"
        : "+f"(c[0]), "+f"(c[1]), "+f"(c[2]), "+f"(c[3])
        : "r"(a0), "r"(a1), "r"(a2), "r"(a3), "r"(b0), "r"(b1));
}

__device__ __forceinline__ void ldsm_x4(unsigned& r0, unsigned& r1, unsigned& r2, unsigned& r3,
                                        unsigned addr) {
    asm volatile("ldmatrix.sync.aligned.m8n8.x4.shared.b16 {%0,%1,%2,%3}, [%4];"
                 : "=r"(r0), "=r"(r1), "=r"(r2), "=r"(r3) : "r"(addr));
}

__device__ __forceinline__ void cp_async16(unsigned dst, const void* src) {
    asm volatile("cp.async.cg.shared.global [%0], [%1], 16;" :: "r"(dst), "l"(src));
}
__device__ __forceinline__ void cp_commit() {
    asm volatile("cp.async.commit_group;");
}
__device__ __forceinline__ void cp_wait_all() {
    asm volatile("cp.async.wait_group 0;");
}

__global__ __launch_bounds__(128) void k_gemm_f16(
    const __half* __restrict__ A, const __half* __restrict__ Wt,
    __half* __restrict__ C1h, int ld1,
    float* __restrict__ C2, int ld2, int nsplit,
    int M, int N, int K,
    const float* __restrict__ bias)
{
    __shared__ __half As_s[2][AHALVES];
    __shared__ __half Bs_s[2][BHALVES];

    const int tid = threadIdx.x;
    const int warp = tid >> 5, lane = tid & 31;
    const int wm = (warp >> 1) * 64;
    const int wn = (warp & 1) * 32;
    const int m0 = blockIdx.y * BM;
    const int n0 = blockIdx.x * BN;
    const int r = lane >> 2, kc = lane & 3;

    float acc[4][4][4];
    #pragma unroll
    for (int a = 0; a < 4; a++)
        #pragma unroll
        for (int b = 0; b < 4; b++)
            #pragma unroll
            for (int c = 0; c < 4; c++) acc[a][b][c] = 0.f;

    const unsigned as0 = (unsigned)__cvta_generic_to_shared(&As_s[0][0]);
    const unsigned bs0 = (unsigned)__cvta_generic_to_shared(&Bs_s[0][0]);

    const int q = lane >> 3, lr = lane & 7;
    const unsigned a_lm = ((wm + (q & 1) * 8 + lr) * APITCH + (q >> 1) * 8) << 1;
    const unsigned b_lm = ((wn + (q >> 1) * 8 + lr) * BPITCH + (q & 1) * 8) << 1;

    const int a_row = tid >> 2, a_c = tid & 3;
    const int b_row = tid >> 2, b_c = tid & 3;

    const int T = K / BK;

    {
        const int k0 = 0;
        #pragma unroll
        for (int j = 0; j < 4; j++) {
            int row = a_row + j * 32;
            int m = m0 + row;
            if (m < M)
                cp_async16(as0 + ((row * APITCH + a_c * 8) << 1),
                           A + (size_t)m * K + k0 + a_c * 8);
        }
        #pragma unroll
        for (int j = 0; j < 2; j++) {
            int row = b_row + j * 32;
            cp_async16(bs0 + ((row * BPITCH + b_c * 8) << 1),
                       Wt + (size_t)(n0 + row) * K + k0 + b_c * 8);
        }
        cp_commit();
    }

    for (int t = 0; t < T; t++) {
        cp_wait_all();
        __syncthreads();

        if (t + 1 < T) {
            const int k0 = (t + 1) * BK;
            const unsigned ab = as0 + ((t + 1) & 1) * (AHALVES * 2);
            const unsigned bb = bs0 + ((t + 1) & 1) * (BHALVES * 2);
            #pragma unroll
            for (int j = 0; j < 4; j++) {
                int row = a_row + j * 32;
                int m = m0 + row;
                if (m < M)
                    cp_async16(ab + ((row * APITCH + a_c * 8) << 1),
                               A + (size_t)m * K + k0 + a_c * 8);
            }
            #pragma unroll
            for (int j = 0; j < 2; j++) {
                int row = b_row + j * 32;
                cp_async16(bb + ((row * BPITCH + b_c * 8) << 1),
                           Wt + (size_t)(n0 + row) * K + k0 + b_c * 8);
            }
            cp_commit();
        }

        const unsigned abuf = as0 + (t & 1) * (AHALVES * 2) + a_lm;
        const unsigned bbuf = bs0 + (t & 1) * (BHALVES * 2) + b_lm;
        #pragma unroll
        for (int g = 0; g < 2; g++) {
            unsigned af[4][4], bf[4][2];
            #pragma unroll
            for (int mt = 0; mt < 4; mt++)
                ldsm_x4(af[mt][0], af[mt][1], af[mt][2], af[mt][3],
                        abuf + ((mt * 16 * APITCH + g * 16) << 1));
            #pragma unroll
            for (int np = 0; np < 2; np++) {
                unsigned r0, r1, r2, r3;
                ldsm_x4(r0, r1, r2, r3, bbuf + ((np * 16 * BPITCH + g * 16) << 1));
                bf[2 * np][0] = r0;  bf[2 * np][1] = r1;
                bf[2 * np + 1][0] = r2;  bf[2 * np + 1][1] = r3;
            }
            #pragma unroll
            for (int mt = 0; mt < 4; mt++)
                #pragma unroll
                for (int nt = 0; nt < 4; nt++)
                    mma_f16(acc[mt][nt], af[mt][0], af[mt][1], af[mt][2], af[mt][3],
                            bf[nt][0], bf[nt][1]);
        }
        __syncthreads();
    }

    #pragma unroll
    for (int mt = 0; mt < 4; mt++) {
        #pragma unroll
        for (int i2 = 0; i2 < 2; i2++) {
            int m = m0 + wm + mt * 16 + r + i2 * 8;
            if (m >= M) continue;
            #pragma unroll
            for (int nt = 0; nt < 4; nt++) {
                int n = n0 + wn + nt * 8 + kc * 2;
                float v0 = acc[mt][nt][i2 * 2 + 0];
                float v1 = acc[mt][nt][i2 * 2 + 1];
                if (bias) { v0 += bias[n]; v1 += bias[n + 1]; }
                if (n < nsplit) {
                    __half2 h = __floats2half2_rn(v0, v1);
                    *(__half2*)(C1h + (size_t)m * ld1 + n) = h;
                } else {
                    *(float2*)(C2 + (size_t)m * ld2 + n - nsplit) = make_float2(v0, v1);
                }
            }
        }
    }
}

// ---------------- fused SpMM + residual epilogue (layer 1: fp16 out) ----------------
__global__ void k_spmm_out96(const __half* __restrict__ feat, const int* __restrict__ rowptr,
                             const int* __restrict__ col, const float* __restrict__ rs_src,
                             const float* __restrict__ raw, const float* __restrict__ rs_in,
                             const float* __restrict__ b1, const float* __restrict__ b2,
                             __half* __restrict__ out, int n_rows) {
    int w = (blockIdx.x * blockDim.x + threadIdx.x) >> 5;
    int lane = threadIdx.x & 31;
    if (w >= n_rows) return;
    int s = rowptr[w], e = rowptr[w + 1];
    bool act = lane < 24;
    int d = lane * 4;
    float4 a0 = make_float4(0.f, 0.f, 0.f, 0.f);
    float4 a1 = make_float4(0.f, 0.f, 0.f, 0.f);
    int i = s;
    for (; i + 3 < e; i += 4) {
        int c0 = col[i], c1 = col[i + 1], c2 = col[i + 2], c3 = col[i + 3];
        float s0 = rs_src[c0], s1 = rs_src[c1], s2 = rs_src[c2], s3 = rs_src[c3];
        if (act) {
            uint2 q0 = *(const uint2*)(feat + (size_t)c0 * 96 + d);
            uint2 q1 = *(const uint2*)(feat + (size_t)c1 * 96 + d);
            uint2 q2 = *(const uint2*)(feat + (size_t)c2 * 96 + d);
            uint2 q3 = *(const uint2*)(feat + (size_t)c3 * 96 + d);
            float2 f;
            f = __half22float2(*(__half2*)&q0.x); a0.x += f.x * s0; a0.y += f.y * s0;
            f = __half22float2(*(__half2*)&q0.y); a0.z += f.x * s0; a0.w += f.y * s0;
            f = __half22float2(*(__half2*)&q1.x); a1.x += f.x * s1; a1.y += f.y * s1;
            f = __half22float2(*(__half2*)&q1.y); a1.z += f.x * s1; a1.w += f.y * s1;
            f = __half22float2(*(__half2*)&q2.x); a0.x += f.x * s2; a0.y += f.y * s2;
            f = __half22float2(*(__half2*)&q2.y); a0.z += f.x * s2; a0.w += f.y * s2;
            f = __half22float2(*(__half2*)&q3.x); a1.x += f.x * s3; a1.y += f.y * s3;
            f = __half22float2(*(__half2*)&q3.y); a1.z += f.x * s3; a1.w += f.y * s3;
        }
    }
    for (; i < e; i++) {
        int c0 = col[i];
        float s0 = rs_src[c0];
        if (act) {
            uint2 q0 = *(const uint2*)(feat + (size_t)c0 * 96 + d);
            float2 f;
            f = __half22float2(*(__half2*)&q0.x); a0.x += f.x * s0; a0.y += f.y * s0;
            f = __half22float2(*(__half2*)&q0.y); a0.z += f.x * s0; a0.w += f.y * s0;
        }
    }
    if (act) {
        float sc = rs_in[w];
        float4 r4 = *(const float4*)(raw + (size_t)w * 96 + d);
        float ox = fmaxf(r4.x + b1[d + 0] + b2[d + 0] + (a0.x + a1.x) * sc, 0.f);
        float oy = fmaxf(r4.y + b1[d + 1] + b2[d + 1] + (a0.y + a1.y) * sc, 0.f);
        float oz = fmaxf(r4.z + b1[d + 2] + b2[d + 2] + (a0.z + a1.z) * sc, 0.f);
        float ow = fmaxf(r4.w + b1[d + 3] + b2[d + 3] + (a0.w + a1.w) * sc, 0.f);
        union { __half2 h[2]; uint2 q; } cv;
        cv.h[0] = __floats2half2_rn(ox, oy);
        cv.h[1] = __floats2half2_rn(oz, ow);
        *(uint2*)(out + (size_t)w * 96 + d) = cv.q;
    }
}

// layer 2 (D=64): HALF-WARP per row (16 lanes), fp32 out + fused inverse-norm
__global__ void k_spmm_out64_norm(const __half* __restrict__ feat, const int* __restrict__ rowptr,
                                  const int* __restrict__ col, const float* __restrict__ rs_src,
                                  const float* __restrict__ raw, const float* __restrict__ rs_in,
                                  const float* __restrict__ b1, const float* __restrict__ b2,
                                  float* __restrict__ out, float* __restrict__ invn, int n_rows) {
    int gt = blockIdx.x * blockDim.x + threadIdx.x;
    int w = gt >> 4;
    int lane = threadIdx.x & 15;
    if (w >= n_rows) return;
    int s = rowptr[w], e = rowptr[w + 1];
    int d = lane * 4;
    float4 a0 = make_float4(0.f, 0.f, 0.f, 0.f);
    float4 a1 = make_float4(0.f, 0.f, 0.f, 0.f);
    int i = s;
    for (; i + 3 < e; i += 4) {
        int c0 = col[i], c1 = col[i + 1], c2 = col[i + 2], c3 = col[i + 3];
        float s0 = rs_src[c0], s1 = rs_src[c1], s2 = rs_src[c2], s3 = rs_src[c3];
        uint2 q0 = *(const uint2*)(feat + (size_t)c0 * 64 + d);
        uint2 q1 = *(const uint2*)(feat + (size_t)c1 * 64 + d);
        uint2 q2 = *(const uint2*)(feat + (size_t)c2 * 64 + d);
        uint2 q3 = *(const uint2*)(feat + (size_t)c3 * 64 + d);
        float2 f;
        f = __half22float2(*(__half2*)&q0.x); a0.x += f.x * s0; a0.y += f.y * s0;
        f = __half22float2(*(__half2*)&q0.y); a0.z += f.x * s0; a0.w += f.y * s0;
        f = __half22float2(*(__half2*)&q1.x); a1.x += f.x * s1; a1.y += f.y * s1;
        f = __half22float2(*(__half2*)&q1.y); a1.z += f.x * s1; a1.w += f.y * s1;
        f = __half22float2(*(__half2*)&q2.x); a0.x += f.x * s2; a0.y += f.y * s2;
        f = __half22float2(*(__half2*)&q2.y); a0.z += f.x * s2; a0.w += f.y * s2;
        f = __half22float2(*(__half2*)&q3.x); a1.x += f.x * s3; a1.y += f.y * s3;
        f = __half22float2(*(__half2*)&q3.y); a1.z += f.x * s3; a1.w += f.y * s3;
    }
    for (; i < e; i++) {
        int c0 = col[i];
        float s0 = rs_src[c0];
        uint2 q0 = *(const uint2*)(feat + (size_t)c0 * 64 + d);
        float2 f;
        f = __half22float2(*(__half2*)&q0.x); a0.x += f.x * s0; a0.y += f.y * s0;
        f = __half22float2(*(__half2*)&q0.y); a0.z += f.x * s0; a0.w += f.y * s0;
    }
    float sq;
    {
        float sc = rs_in[w];
        float4 r4 = *(const float4*)(raw + (size_t)w * 64 + d);
        float4 o;
        o.x = fmaxf(r4.x + b1[d + 0] + b2[d + 0] + (a0.x + a1.x) * sc, 0.f);
        o.y = fmaxf(r4.y + b1[d + 1] + b2[d + 1] + (a0.y + a1.y) * sc, 0.f);
        o.z = fmaxf(r4.z + b1[d + 2] + b2[d + 2] + (a0.z + a1.z) * sc, 0.f);
        o.w = fmaxf(r4.w + b1[d + 3] + b2[d + 3] + (a0.w + a1.w) * sc, 0.f);
        *(float4*)(out + (size_t)w * 64 + d) = o;
        sq = o.x * o.x + o.y * o.y + o.z * o.z + o.w * o.w;
    }
    #pragma unroll
    for (int off = 8; off; off >>= 1) sq += __shfl_xor_sync(0xffffffffu, sq, off);
    if (lane == 0) invn[w] = 1.0f / fmaxf(sqrtf(sq), 1e-12f);
}

// ---------------- score: half-warp per pair, float4 loads ----------------
__global__ void k_score_all(const float* __restrict__ hu, const float* __restrict__ hr,
                            const float* __restrict__ invn_u, const float* __restrict__ invn_r,
                            const int* __restrict__ pos_u, const int* __restrict__ pos_r,
                            const int* __restrict__ neg_u, const int* __restrict__ neg_r,
                            float* __restrict__ out) {
    int gt = blockIdx.x * blockDim.x + threadIdx.x;
    int w = gt >> 4;               // half-warp per pair
    int lane = threadIdx.x & 15;
    if (w >= 2 * NEP) return;
    int u, r;
    if (w < NEP) { u = pos_u[w]; r = pos_r[w]; }
    else         { u = neg_u[w - NEP]; r = neg_r[w - NEP]; }
    float4 a4 = *(const float4*)(hu + (size_t)u * D_OUT + lane * 4);
    float4 b4 = *(const float4*)(hr + (size_t)r * D_OUT + lane * 4);
    float s = a4.x * b4.x + a4.y * b4.y + a4.z * b4.z + a4.w * b4.w;
    #pragma unroll
    for (int off = 8; off; off >>= 1) s += __shfl_xor_sync(0xffffffffu, s, off);
    if (lane == 0) out[w] = s * invn_u[u] * invn_r[r];
}

// ---------------- host ----------------
static inline void* sym(const void* s) {
    void* p = nullptr;
    cudaGetSymbolAddress(&p, s);
    return p;
}

extern "C" void kernel_launch(void* const* d_in, const int* in_sizes, int n_in,
                              void* d_out, int out_size) {
    const float* user_feat = (const float*)d_in[0];
    const float* repo_feat = (const float*)d_in[1];
    const float* W_ue = (const float*)d_in[2];   const float* b_ue = (const float*)d_in[3];
    const float* W_re = (const float*)d_in[4];   const float* b_re = (const float*)d_in[5];
    const float* W_hid_ur = (const float*)d_in[6];  const float* b_hid_ur = (const float*)d_in[7];
    const float* W_hid_ru = (const float*)d_in[8];  const float* b_hid_ru = (const float*)d_in[9];
    const float* W_out_ur = (const float*)d_in[10]; const float* b_out_ur = (const float*)d_in[11];
    const float* W_out_ru = (const float*)d_in[12]; const float* b_out_ru = (const float*)d_in[13];
    const float* W_hcu = (const float*)d_in[14]; const float* b_hcu = (const float*)d_in[15];
    const float* W_hcr = (const float*)d_in[16]; const float* b_hcr = (const float*)d_in[17];
    const float* W_ocu = (const float*)d_in[18]; const float* b_ocu = (const float*)d_in[19];
    const float* W_ocr = (const float*)d_in[20]; const float* b_ocr = (const float*)d_in[21];
    const int* e_ur_src = (const int*)d_in[22];
    const int* e_ur_dst = (const int*)d_in[23];
    const int* e_ru_src = (const int*)d_in[24];
    const int* e_ru_dst = (const int*)d_in[25];
    const int* pos_u = (const int*)d_in[26];
    const int* pos_r = (const int*)d_in[27];
    const int* neg_u = (const int*)d_in[28];
    const int* neg_r = (const int*)d_in[29];
    float* out = (float*)d_out;

    __half* a_user = (__half*)sym(g_a_user);
    __half* a_repo = (__half*)sym(g_a_repo);
    __half* feat_u = (__half*)sym(g_feat_u);
    __half* feat_r = (__half*)sym(g_feat_r);
    float*  raw_u  = (float*)sym(g_raw_u);
    float*  raw_r  = (float*)sym(g_raw_r);
    __half* out_user = (__half*)sym(g_out_user);
    __half* out_repo = (__half*)sym(g_out_repo);
    float*  new_user = (float*)sym(g_new_user);
    float*  new_repo = (float*)sym(g_new_repo);
    int* cnt_u_out = (int*)sym(g_cnt_u_out);
    int* cnt_u_in  = (int*)sym(g_cnt_u_in);
    int* cnt_r_out = (int*)sym(g_cnt_r_out);
    int* cnt_r_in  = (int*)sym(g_cnt_r_in);
    float* rs_u_out = (float*)sym(g_rs_u_out);
    float* rs_u_in  = (float*)sym(g_rs_u_in);
    float* rs_r_out = (float*)sym(g_rs_r_out);
    float* rs_r_in  = (float*)sym(g_rs_r_in);
    int* rowptr_ur = (int*)sym(g_rowptr_ur);
    int* rowptr_ru = (int*)sym(g_rowptr_ru);
    int* cursor_ur = (int*)sym(g_cursor_ur);
    int* cursor_ru = (int*)sym(g_cursor_ru);
    int* col_ur = (int*)sym(g_col_ur);
    int* col_ru = (int*)sym(g_col_ru);
    int* part   = (int*)sym(g_part);
    float* invn_u = (float*)sym(g_invn_u);
    float* invn_r = (float*)sym(g_invn_r);
    __half* WCt_u1 = (__half*)sym(g_WCt_u1);
    __half* WCt_r1 = (__half*)sym(g_WCt_r1);
    float* bc_u1 = (float*)sym(g_bc_u1);
    float* bc_r1 = (float*)sym(g_bc_r1);
    __half* wc2t_u = (__half*)sym(g_wc2t_u);
    __half* wc2t_r = (__half*)sym(g_wc2t_r);

    const int T = 256;
    auto blocks = [](long n, int t) { return (int)((n + t - 1) / t); };

    cudaMemsetAsync(cnt_u_out, 0, N_USER * sizeof(int), 0);
    cudaMemsetAsync(cnt_u_in,  0, N_USER * sizeof(int), 0);
    cudaMemsetAsync(cnt_r_out, 0, N_REPO * sizeof(int), 0);
    cudaMemsetAsync(cnt_r_in,  0, N_REPO * sizeof(int), 0);

    k_tofp16<<<blocks((long)NU8 + NR8, T), T>>>(user_feat, repo_feat);
    k_pack2<<<blocks(2 * 128 * 96, T), T>>>(W_out_ur, W_ocu, W_out_ru, W_ocr);
    k_fold<<<blocks(2L * D_IN * 192 + 384, T), T>>>(W_ue, b_ue, W_hid_ur, W_hcu,
                                                    W_re, b_re, W_hid_ru, W_hcr);

    dim3 tb(128);
    auto grid = [](int M, int N) { return dim3(N / BN, (M + BM - 1) / BM); };

    // layer-1 fused GEMMs: Xh @ WCt^T + bc -> [feat fp16 | raw fp32]
    k_gemm_f16<<<grid(N_REPO, 192), tb>>>(a_repo, WCt_r1,
        feat_r, D_HID, raw_r, D_HID, D_HID, N_REPO, 192, D_IN, bc_r1);
    k_gemm_f16<<<grid(N_USER, 192), tb>>>(a_user, WCt_u1,
        feat_u, D_HID, raw_u, D_HID, D_HID, N_USER, 192, D_IN, bc_u1);

    // graph structure
    k_count_all<<<blocks(2L * NE, T), T>>>(e_ur_src, e_ur_dst, e_ru_src, e_ru_dst);
    k_rsqrt_all<<<blocks(2L * (N_USER + N_REPO), T), T>>>();
    int nb_r = (N_REPO + 1023) / 1024;
    int nb_u = (N_USER + 1023) / 1024;
    k_scan_block<<<nb_r, 1024>>>(cnt_r_in, rowptr_ur, part, N_REPO);
    k_scan_part<<<1, 128>>>(part, nb_r);
    k_scan_add<<<blocks(N_REPO, T), T>>>(rowptr_ur, cursor_ur, part, N_REPO);
    k_scan_block<<<nb_u, 1024>>>(cnt_u_in, rowptr_ru, part, N_USER);
    k_scan_part<<<1, 128>>>(part, nb_u);
    k_scan_add<<<blocks(N_USER, T), T>>>(rowptr_ru, cursor_ru, part, N_USER);
    k_fill_all<<<blocks(2L * NE, T), T>>>(e_ur_src, e_ur_dst, e_ru_src, e_ru_dst);

    // layer-1 SpMM + residual -> fp16 out
    k_spmm_out96<<<blocks(N_USER * 32L, T), T>>>(feat_r, rowptr_ru, col_ru, rs_r_out,
                                                 raw_u, rs_u_in, b_hcu, b_hid_ru,
                                                 out_user, N_USER);
    k_spmm_out96<<<blocks(N_REPO * 32L, T), T>>>(feat_u, rowptr_ur, col_ur, rs_u_out,
                                                 raw_r, rs_r_in, b_hcr, b_hid_ur,
                                                 out_repo, N_REPO);

    // layer-2 GEMMs (K=96)
    k_gemm_f16<<<grid(N_REPO, 128), tb>>>(out_repo, wc2t_r,
        feat_r, D_OUT, raw_r, D_OUT, D_OUT, N_REPO, 128, D_HID, nullptr);
    k_gemm_f16<<<grid(N_USER, 128), tb>>>(out_user, wc2t_u,
        feat_u, D_OUT, raw_u, D_OUT, D_OUT, N_USER, 128, D_HID, nullptr);

    // layer-2 SpMM + residual + norm (half-warp per row)
    k_spmm_out64_norm<<<blocks(N_USER * 16L, T), T>>>(feat_r, rowptr_ru, col_ru, rs_r_out,
                                                      raw_u, rs_u_in, b_ocu, b_out_ru,
                                                      new_user, invn_u, N_USER);
    k_spmm_out64_norm<<<blocks(N_REPO * 16L, T), T>>>(feat_u, rowptr_ur, col_ur, rs_u_out,
                                                      raw_r, rs_r_in, b_ocr, b_out_ur,
                                                      new_repo, invn_r, N_REPO);

    // cosine scores (half-warp per pair)
    k_score_all<<<blocks(2L * NEP * 16, T), T>>>(new_user, new_repo, invn_u, invn_r,
                                                 pos_u, pos_r, neg_u, neg_r, out);
}

// round 15
// speedup vs baseline: 1.0934x; 1.0089x over previous
#include <cuda_runtime.h>
#include <cuda_fp16.h>
#include <math.h>

// ---------------- problem constants ----------------
#define N_USER 50000
#define N_REPO 100000
#define NE     1000000
#define NEP    200000
#define D_IN   256
#define D_EMB  125
#define D_HID  96
#define D_OUT  64

// ---------------- scratch (device globals) ----------------
__device__ __align__(16) __half g_a_user[N_USER * D_IN];
__device__ __align__(16) __half g_a_repo[N_REPO * D_IN];
__device__ __align__(16) __half g_feat_u[N_USER * D_HID];
__device__ __align__(16) __half g_feat_r[N_REPO * D_HID];
__device__ float  g_raw_u [N_USER * D_HID];
__device__ float  g_raw_r [N_REPO * D_HID];
__device__ __align__(16) __half g_out_user[N_USER * D_HID];
__device__ __align__(16) __half g_out_repo[N_REPO * D_HID];
__device__ float  g_new_user[N_USER * D_OUT];
__device__ float  g_new_repo[N_REPO * D_OUT];

__device__ int   g_cnt_u_out[N_USER];
__device__ int   g_cnt_u_in [N_USER];
__device__ int   g_cnt_r_out[N_REPO];
__device__ int   g_cnt_r_in [N_REPO];
__device__ float g_rs_u_out[N_USER], g_rs_u_in[N_USER];
__device__ float g_rs_r_out[N_REPO], g_rs_r_in[N_REPO];

__device__ int g_rowptr_ur[N_REPO + 1];
__device__ int g_rowptr_ru[N_USER + 1];
__device__ int g_cursor_ur[N_REPO];
__device__ int g_cursor_ru[N_USER];
__device__ int g_col_ur[NE];
__device__ int g_col_ru[NE];
__device__ int g_part[128];

__device__ float g_invn_u[N_USER];
__device__ float g_invn_r[N_REPO];

__device__ __align__(16) __half g_WCt_u1[192 * D_IN];
__device__ __align__(16) __half g_WCt_r1[192 * D_IN];
__device__ float g_bc_u1[192];
__device__ float g_bc_r1[192];
__device__ __align__(16) __half g_wc2t_u[128 * D_HID];
__device__ __align__(16) __half g_wc2t_r[128 * D_HID];

// ---------------- preprocessing kernels ----------------
__global__ void k_pack2(const float* __restrict__ W_out_ur, const float* __restrict__ W_ocu,
                        const float* __restrict__ W_out_ru, const float* __restrict__ W_ocr) {
    int i = blockIdx.x * blockDim.x + threadIdx.x;
    if (i >= 2 * 128 * 96) return;
    int half_sel = i / (128 * 96);
    int j = i - half_sel * (128 * 96);
    int n = j / 96, k = j % 96;
    const float* Wa = half_sel ? W_out_ru : W_out_ur;
    const float* Wb = half_sel ? W_ocr    : W_ocu;
    float v = (n < 64) ? Wa[k * 64 + n] : Wb[k * 64 + (n - 64)];
    __half* dst = half_sel ? g_wc2t_r : g_wc2t_u;
    dst[n * 96 + k] = __float2half_rn(v);
}

__global__ void k_fold(const float* __restrict__ W_ue, const float* __restrict__ b_ue,
                       const float* __restrict__ W_hid_ur, const float* __restrict__ W_hcu,
                       const float* __restrict__ W_re, const float* __restrict__ b_re,
                       const float* __restrict__ W_hid_ru, const float* __restrict__ W_hcr) {
    const int PER = D_IN * 192;
    int i = blockIdx.x * blockDim.x + threadIdx.x;
    if (i < 2 * PER) {
        const float* We = (i < PER) ? W_ue : W_re;
        const float* Wm = (i < PER) ? W_hid_ur : W_hid_ru;
        const float* Wr = (i < PER) ? W_hcu : W_hcr;
        __half* WCt = (i < PER) ? g_WCt_u1 : g_WCt_r1;
        int j = (i < PER) ? i : i - PER;
        int n = j / D_IN, m = j % D_IN;
        const float* Wx = (n < 96) ? (Wm + n) : (Wr + n - 96);
        float a = 0.f;
        #pragma unroll 5
        for (int k = 0; k < D_EMB; k++) a += We[m * D_EMB + k] * Wx[k * 96];
        WCt[n * D_IN + m] = __float2half_rn(a);
        return;
    }
    i -= 2 * PER;
    if (i < 384) {
        const float* be = (i < 192) ? b_ue : b_re;
        const float* Wm = (i < 192) ? W_hid_ur : W_hid_ru;
        const float* Wr = (i < 192) ? W_hcu : W_hcr;
        float* bc = (i < 192) ? g_bc_u1 : g_bc_r1;
        int n = i % 192;
        const float* Wx = (n < 96) ? (Wm + n) : (Wr + n - 96);
        float a = 0.f;
        for (int k = 0; k < D_EMB; k++) a += be[k] * Wx[k * 96];
        bc[n] = a;
    }
}

// fp32 -> fp16: 8 floats per thread (2x LDG.128 -> 1x STG.128)
#define NU8 (N_USER * (D_IN / 8))
#define NR8 (N_REPO * (D_IN / 8))
__global__ void k_tofp16(const float* __restrict__ u, const float* __restrict__ r) {
    long i = blockIdx.x * (long)blockDim.x + threadIdx.x;
    const float4* src;
    uint4* dst;
    long j;
    if (i < NU8) { src = (const float4*)u; dst = (uint4*)g_a_user; j = i; }
    else if (i < NU8 + NR8) { src = (const float4*)r; dst = (uint4*)g_a_repo; j = i - NU8; }
    else return;
    float4 v0 = src[2 * j];
    float4 v1 = src[2 * j + 1];
    union { __half2 h[4]; uint4 q; } cv;
    cv.h[0] = __floats2half2_rn(v0.x, v0.y);
    cv.h[1] = __floats2half2_rn(v0.z, v0.w);
    cv.h[2] = __floats2half2_rn(v1.x, v1.y);
    cv.h[3] = __floats2half2_rn(v1.z, v1.w);
    dst[j] = cv.q;
}

__global__ void k_count_all(const int* __restrict__ ur_src, const int* __restrict__ ur_dst,
                            const int* __restrict__ ru_src, const int* __restrict__ ru_dst) {
    int i = blockIdx.x * blockDim.x + threadIdx.x;
    if (i < NE) {
        atomicAdd(&g_cnt_u_out[ur_src[i]], 1);
        atomicAdd(&g_cnt_r_in[ur_dst[i]], 1);
    } else if (i < 2 * NE) {
        int j = i - NE;
        atomicAdd(&g_cnt_r_out[ru_src[j]], 1);
        atomicAdd(&g_cnt_u_in[ru_dst[j]], 1);
    }
}

__global__ void k_rsqrt_all() {
    int i = blockIdx.x * blockDim.x + threadIdx.x;
    if (i < N_USER) { g_rs_u_out[i] = rsqrtf(fmaxf((float)g_cnt_u_out[i], 1.f)); return; }
    i -= N_USER;
    if (i < N_USER) { g_rs_u_in[i] = rsqrtf(fmaxf((float)g_cnt_u_in[i], 1.f)); return; }
    i -= N_USER;
    if (i < N_REPO) { g_rs_r_out[i] = rsqrtf(fmaxf((float)g_cnt_r_out[i], 1.f)); return; }
    i -= N_REPO;
    if (i < N_REPO) { g_rs_r_in[i] = rsqrtf(fmaxf((float)g_cnt_r_in[i], 1.f)); return; }
}

__global__ void k_scan_block(const int* __restrict__ cnt, int* rowptr, int* partial, int n) {
    __shared__ int sh[1024];
    int b = blockIdx.x, t = threadIdx.x;
    int i = b * 1024 + t;
    int v = (i < n) ? cnt[i] : 0;
    sh[t] = v;
    __syncthreads();
    for (int off = 1; off < 1024; off <<= 1) {
        int x = (t >= off) ? sh[t - off] : 0;
        __syncthreads();
        sh[t] += x;
        __syncthreads();
    }
    if (i < n) rowptr[i + 1] = sh[t];
    if (t == 1023) partial[b] = sh[1023];
}

__global__ void k_scan_part(int* partial, int nb) {
    __shared__ int sh[128];
    int t = threadIdx.x;
    int v = (t < nb) ? partial[t] : 0;
    sh[t] = v;
    __syncthreads();
    for (int off = 1; off < 128; off <<= 1) {
        int x = (t >= off) ? sh[t - off] : 0;
        __syncthreads();
        sh[t] += x;
        __syncthreads();
    }
    if (t < nb) partial[t] = sh[t] - v;
}

__global__ void k_scan_add(int* rowptr, int* cursor, const int* __restrict__ partial, int n) {
    int i = blockIdx.x * blockDim.x + threadIdx.x;
    if (i == 0) { rowptr[0] = 0; cursor[0] = 0; }
    if (i < n) {
        int v = rowptr[i + 1] + partial[i >> 10];
        rowptr[i + 1] = v;
        if (i + 1 < n) cursor[i + 1] = v;
    }
}

__global__ void k_fill_all(const int* __restrict__ ur_src, const int* __restrict__ ur_dst,
                           const int* __restrict__ ru_src, const int* __restrict__ ru_dst) {
    int i = blockIdx.x * blockDim.x + threadIdx.x;
    if (i < NE) {
        int p = atomicAdd(&g_cursor_ur[ur_dst[i]], 1);
        g_col_ur[p] = ur_src[i];
    } else if (i < 2 * NE) {
        int j = i - NE;
        int p = atomicAdd(&g_cursor_ru[ru_dst[j]], 1);
        g_col_ru[p] = ru_src[j];
    }
}

// ---------------- fp16 GEMM: 3-stage cp.async + ldmatrix + m16n8k16 ----------------
// 128 threads, 4 warps 2x2, warp tile 64x32; 3 smem stages (46 KB, still 4 blocks/SM)
#define BM 128
#define BN 64
#define BK 32
#define APITCH 40
#define BPITCH 40
#define AHALVES (BM * APITCH)
#define BHALVES (BN * BPITCH)

__device__ __forceinline__ void mma_f16(float c[4],
                                        unsigned a0, unsigned a1, unsigned a2, unsigned a3,
                                        unsigned b0, unsigned b1) {
    asm volatile(
        "mma.sync.aligned.m16n8k16.row.col.f32.f16.f16.f32 "
        "{%0,%1,%2,%3}, {%4,%5,%6,%7}, {%8,%9}, {%0,%1,%2,%3};"
        : "+f"(c[0]), "+f"(c[1]), "+f"(c[2]), "+f"(c[3])
        : "r"(a0), "r"(a1), "r"(a2), "r"(a3), "r"(b0), "r"(b1));
}

__device__ __forceinline__ void ldsm_x4(unsigned& r0, unsigned& r1, unsigned& r2, unsigned& r3,
                                        unsigned addr) {
    asm volatile("ldmatrix.sync.aligned.m8n8.x4.shared.b16 {%0,%1,%2,%3}, [%4];"
                 : "=r"(r0), "=r"(r1), "=r"(r2), "=r"(r3) : "r"(addr));
}

__device__ __forceinline__ void cp_async16(unsigned dst, const void* src) {
    asm volatile("cp.async.cg.shared.global [%0], [%1], 16;" :: "r"(dst), "l"(src));
}
__device__ __forceinline__ void cp_commit() {
    asm volatile("cp.async.commit_group;");
}
template <int N>
__device__ __forceinline__ void cp_wait() {
    asm volatile("cp.async.wait_group %0;" :: "n"(N));
}

__global__ __launch_bounds__(128) void k_gemm_f16(
    const __half* __restrict__ A, const __half* __restrict__ Wt,
    __half* __restrict__ C1h, int ld1,
    float* __restrict__ C2, int ld2, int nsplit,
    int M, int N, int K,
    const float* __restrict__ bias)
{
    __shared__ __half As_s[3][AHALVES];
    __shared__ __half Bs_s[3][BHALVES];

    const int tid = threadIdx.x;
    const int warp = tid >> 5, lane = tid & 31;
    const int wm = (warp >> 1) * 64;
    const int wn = (warp & 1) * 32;
    const int m0 = blockIdx.y * BM;
    const int n0 = blockIdx.x * BN;
    const int r = lane >> 2, kc = lane & 3;

    float acc[4][4][4];
    #pragma unroll
    for (int a = 0; a < 4; a++)
        #pragma unroll
        for (int b = 0; b < 4; b++)
            #pragma unroll
            for (int c = 0; c < 4; c++) acc[a][b][c] = 0.f;

    const unsigned as0 = (unsigned)__cvta_generic_to_shared(&As_s[0][0]);
    const unsigned bs0 = (unsigned)__cvta_generic_to_shared(&Bs_s[0][0]);

    const int q = lane >> 3, lr = lane & 7;
    const unsigned a_lm = ((wm + (q & 1) * 8 + lr) * APITCH + (q >> 1) * 8) << 1;
    const unsigned b_lm = ((wn + (q >> 1) * 8 + lr) * BPITCH + (q & 1) * 8) << 1;

    const int a_row = tid >> 2, a_c = tid & 3;
    const int b_row = tid >> 2, b_c = tid & 3;

    const int T = K / BK;

    auto stage = [&](int t, int buf) {
        const int k0 = t * BK;
        const unsigned ab = as0 + buf * (AHALVES * 2);
        const unsigned bb = bs0 + buf * (BHALVES * 2);
        #pragma unroll
        for (int j = 0; j < 4; j++) {
            int row = a_row + j * 32;
            int m = m0 + row;
            if (m < M)
                cp_async16(ab + ((row * APITCH + a_c * 8) << 1),
                           A + (size_t)m * K + k0 + a_c * 8);
        }
        #pragma unroll
        for (int j = 0; j < 2; j++) {
            int row = b_row + j * 32;
            cp_async16(bb + ((row * BPITCH + b_c * 8) << 1),
                       Wt + (size_t)(n0 + row) * K + k0 + b_c * 8);
        }
        cp_commit();
    };

    // prologue: stage tiles 0 and 1
    stage(0, 0);
    if (T > 1) stage(1, 1);

    for (int t = 0; t < T; t++) {
        if (t + 1 < T) cp_wait<1>(); else cp_wait<0>();
        __syncthreads();

        if (t + 2 < T) stage(t + 2, (t + 2) % 3);

        const int buf = t % 3;
        const unsigned abuf = as0 + buf * (AHALVES * 2) + a_lm;
        const unsigned bbuf = bs0 + buf * (BHALVES * 2) + b_lm;
        #pragma unroll
        for (int g = 0; g < 2; g++) {
            unsigned af[4][4], bf[4][2];
            #pragma unroll
            for (int mt = 0; mt < 4; mt++)
                ldsm_x4(af[mt][0], af[mt][1], af[mt][2], af[mt][3],
                        abuf + ((mt * 16 * APITCH + g * 16) << 1));
            #pragma unroll
            for (int np = 0; np < 2; np++) {
                unsigned r0, r1, r2, r3;
                ldsm_x4(r0, r1, r2, r3, bbuf + ((np * 16 * BPITCH + g * 16) << 1));
                bf[2 * np][0] = r0;  bf[2 * np][1] = r1;
                bf[2 * np + 1][0] = r2;  bf[2 * np + 1][1] = r3;
            }
            #pragma unroll
            for (int mt = 0; mt < 4; mt++)
                #pragma unroll
                for (int nt = 0; nt < 4; nt++)
                    mma_f16(acc[mt][nt], af[mt][0], af[mt][1], af[mt][2], af[mt][3],
                            bf[nt][0], bf[nt][1]);
        }
        __syncthreads();
    }

    #pragma unroll
    for (int mt = 0; mt < 4; mt++) {
        #pragma unroll
        for (int i2 = 0; i2 < 2; i2++) {
            int m = m0 + wm + mt * 16 + r + i2 * 8;
            if (m >= M) continue;
            #pragma unroll
            for (int nt = 0; nt < 4; nt++) {
                int n = n0 + wn + nt * 8 + kc * 2;
                float v0 = acc[mt][nt][i2 * 2 + 0];
                float v1 = acc[mt][nt][i2 * 2 + 1];
                if (bias) { v0 += bias[n]; v1 += bias[n + 1]; }
                if (n < nsplit) {
                    __half2 h = __floats2half2_rn(v0, v1);
                    *(__half2*)(C1h + (size_t)m * ld1 + n) = h;
                } else {
                    *(float2*)(C2 + (size_t)m * ld2 + n - nsplit) = make_float2(v0, v1);
                }
            }
        }
    }
}

// ---------------- fused SpMM + residual epilogue (layer 1: fp16 out) ----------------
__global__ void k_spmm_out96(const __half* __restrict__ feat, const int* __restrict__ rowptr,
                             const int* __restrict__ col, const float* __restrict__ rs_src,
                             const float* __restrict__ raw, const float* __restrict__ rs_in,
                             const float* __restrict__ b1, const float* __restrict__ b2,
                             __half* __restrict__ out, int n_rows) {
    int w = (blockIdx.x * blockDim.x + threadIdx.x) >> 5;
    int lane = threadIdx.x & 31;
    if (w >= n_rows) return;
    int s = rowptr[w], e = rowptr[w + 1];
    bool act = lane < 24;
    int d = lane * 4;
    float4 a0 = make_float4(0.f, 0.f, 0.f, 0.f);
    float4 a1 = make_float4(0.f, 0.f, 0.f, 0.f);
    int i = s;
    for (; i + 3 < e; i += 4) {
        int c0 = col[i], c1 = col[i + 1], c2 = col[i + 2], c3 = col[i + 3];
        float s0 = rs_src[c0], s1 = rs_src[c1], s2 = rs_src[c2], s3 = rs_src[c3];
        if (act) {
            uint2 q0 = *(const uint2*)(feat + (size_t)c0 * 96 + d);
            uint2 q1 = *(const uint2*)(feat + (size_t)c1 * 96 + d);
            uint2 q2 = *(const uint2*)(feat + (size_t)c2 * 96 + d);
            uint2 q3 = *(const uint2*)(feat + (size_t)c3 * 96 + d);
            float2 f;
            f = __half22float2(*(__half2*)&q0.x); a0.x += f.x * s0; a0.y += f.y * s0;
            f = __half22float2(*(__half2*)&q0.y); a0.z += f.x * s0; a0.w += f.y * s0;
            f = __half22float2(*(__half2*)&q1.x); a1.x += f.x * s1; a1.y += f.y * s1;
            f = __half22float2(*(__half2*)&q1.y); a1.z += f.x * s1; a1.w += f.y * s1;
            f = __half22float2(*(__half2*)&q2.x); a0.x += f.x * s2; a0.y += f.y * s2;
            f = __half22float2(*(__half2*)&q2.y); a0.z += f.x * s2; a0.w += f.y * s2;
            f = __half22float2(*(__half2*)&q3.x); a1.x += f.x * s3; a1.y += f.y * s3;
            f = __half22float2(*(__half2*)&q3.y); a1.z += f.x * s3; a1.w += f.y * s3;
        }
    }
    for (; i < e; i++) {
        int c0 = col[i];
        float s0 = rs_src[c0];
        if (act) {
            uint2 q0 = *(const uint2*)(feat + (size_t)c0 * 96 + d);
            float2 f;
            f = __half22float2(*(__half2*)&q0.x); a0.x += f.x * s0; a0.y += f.y * s0;
            f = __half22float2(*(__half2*)&q0.y); a0.z += f.x * s0; a0.w += f.y * s0;
        }
    }
    if (act) {
        float sc = rs_in[w];
        float4 r4 = *(const float4*)(raw + (size_t)w * 96 + d);
        float ox = fmaxf(r4.x + b1[d + 0] + b2[d + 0] + (a0.x + a1.x) * sc, 0.f);
        float oy = fmaxf(r4.y + b1[d + 1] + b2[d + 1] + (a0.y + a1.y) * sc, 0.f);
        float oz = fmaxf(r4.z + b1[d + 2] + b2[d + 2] + (a0.z + a1.z) * sc, 0.f);
        float ow = fmaxf(r4.w + b1[d + 3] + b2[d + 3] + (a0.w + a1.w) * sc, 0.f);
        union { __half2 h[2]; uint2 q; } cv;
        cv.h[0] = __floats2half2_rn(ox, oy);
        cv.h[1] = __floats2half2_rn(oz, ow);
        *(uint2*)(out + (size_t)w * 96 + d) = cv.q;
    }
}

// layer 2 (D=64): HALF-WARP per row (16 lanes), fp32 out + fused inverse-norm
__global__ void k_spmm_out64_norm(const __half* __restrict__ feat, const int* __restrict__ rowptr,
                                  const int* __restrict__ col, const float* __restrict__ rs_src,
                                  const float* __restrict__ raw, const float* __restrict__ rs_in,
                                  const float* __restrict__ b1, const float* __restrict__ b2,
                                  float* __restrict__ out, float* __restrict__ invn, int n_rows) {
    int gt = blockIdx.x * blockDim.x + threadIdx.x;
    int w = gt >> 4;
    int lane = threadIdx.x & 15;
    if (w >= n_rows) return;
    int s = rowptr[w], e = rowptr[w + 1];
    int d = lane * 4;
    float4 a0 = make_float4(0.f, 0.f, 0.f, 0.f);
    float4 a1 = make_float4(0.f, 0.f, 0.f, 0.f);
    int i = s;
    for (; i + 3 < e; i += 4) {
        int c0 = col[i], c1 = col[i + 1], c2 = col[i + 2], c3 = col[i + 3];
        float s0 = rs_src[c0], s1 = rs_src[c1], s2 = rs_src[c2], s3 = rs_src[c3];
        uint2 q0 = *(const uint2*)(feat + (size_t)c0 * 64 + d);
        uint2 q1 = *(const uint2*)(feat + (size_t)c1 * 64 + d);
        uint2 q2 = *(const uint2*)(feat + (size_t)c2 * 64 + d);
        uint2 q3 = *(const uint2*)(feat + (size_t)c3 * 64 + d);
        float2 f;
        f = __half22float2(*(__half2*)&q0.x); a0.x += f.x * s0; a0.y += f.y * s0;
        f = __half22float2(*(__half2*)&q0.y); a0.z += f.x * s0; a0.w += f.y * s0;
        f = __half22float2(*(__half2*)&q1.x); a1.x += f.x * s1; a1.y += f.y * s1;
        f = __half22float2(*(__half2*)&q1.y); a1.z += f.x * s1; a1.w += f.y * s1;
        f = __half22float2(*(__half2*)&q2.x); a0.x += f.x * s2; a0.y += f.y * s2;
        f = __half22float2(*(__half2*)&q2.y); a0.z += f.x * s2; a0.w += f.y * s2;
        f = __half22float2(*(__half2*)&q3.x); a1.x += f.x * s3; a1.y += f.y * s3;
        f = __half22float2(*(__half2*)&q3.y); a1.z += f.x * s3; a1.w += f.y * s3;
    }
    for (; i < e; i++) {
        int c0 = col[i];
        float s0 = rs_src[c0];
        uint2 q0 = *(const uint2*)(feat + (size_t)c0 * 64 + d);
        float2 f;
        f = __half22float2(*(__half2*)&q0.x); a0.x += f.x * s0; a0.y += f.y * s0;
        f = __half22float2(*(__half2*)&q0.y); a0.z += f.x * s0; a0.w += f.y * s0;
    }
    float sq;
    {
        float sc = rs_in[w];
        float4 r4 = *(const float4*)(raw + (size_t)w * 64 + d);
        float4 o;
        o.x = fmaxf(r4.x + b1[d + 0] + b2[d + 0] + (a0.x + a1.x) * sc, 0.f);
        o.y = fmaxf(r4.y + b1[d + 1] + b2[d + 1] + (a0.y + a1.y) * sc, 0.f);
        o.z = fmaxf(r4.z + b1[d + 2] + b2[d + 2] + (a0.z + a1.z) * sc, 0.f);
        o.w = fmaxf(r4.w + b1[d + 3] + b2[d + 3] + (a0.w + a1.w) * sc, 0.f);
        *(float4*)(out + (size_t)w * 64 + d) = o;
        sq = o.x * o.x + o.y * o.y + o.z * o.z + o.w * o.w;
    }
    #pragma unroll
    for (int off = 8; off; off >>= 1) sq += __shfl_xor_sync(0xffffffffu, sq, off);
    if (lane == 0) invn[w] = 1.0f / fmaxf(sqrtf(sq), 1e-12f);
}

// ---------------- score: half-warp per pair, float4 loads ----------------
__global__ void k_score_all(const float* __restrict__ hu, const float* __restrict__ hr,
                            const float* __restrict__ invn_u, const float* __restrict__ invn_r,
                            const int* __restrict__ pos_u, const int* __restrict__ pos_r,
                            const int* __restrict__ neg_u, const int* __restrict__ neg_r,
                            float* __restrict__ out) {
    int gt = blockIdx.x * blockDim.x + threadIdx.x;
    int w = gt >> 4;
    int lane = threadIdx.x & 15;
    if (w >= 2 * NEP) return;
    int u, r;
    if (w < NEP) { u = pos_u[w]; r = pos_r[w]; }
    else         { u = neg_u[w - NEP]; r = neg_r[w - NEP]; }
    float4 a4 = *(const float4*)(hu + (size_t)u * D_OUT + lane * 4);
    float4 b4 = *(const float4*)(hr + (size_t)r * D_OUT + lane * 4);
    float s = a4.x * b4.x + a4.y * b4.y + a4.z * b4.z + a4.w * b4.w;
    #pragma unroll
    for (int off = 8; off; off >>= 1) s += __shfl_xor_sync(0xffffffffu, s, off);
    if (lane == 0) out[w] = s * invn_u[u] * invn_r[r];
}

// ---------------- host ----------------
static inline void* sym(const void* s) {
    void* p = nullptr;
    cudaGetSymbolAddress(&p, s);
    return p;
}

extern "C" void kernel_launch(void* const* d_in, const int* in_sizes, int n_in,
                              void* d_out, int out_size) {
    const float* user_feat = (const float*)d_in[0];
    const float* repo_feat = (const float*)d_in[1];
    const float* W_ue = (const float*)d_in[2];   const float* b_ue = (const float*)d_in[3];
    const float* W_re = (const float*)d_in[4];   const float* b_re = (const float*)d_in[5];
    const float* W_hid_ur = (const float*)d_in[6];  const float* b_hid_ur = (const float*)d_in[7];
    const float* W_hid_ru = (const float*)d_in[8];  const float* b_hid_ru = (const float*)d_in[9];
    const float* W_out_ur = (const float*)d_in[10]; const float* b_out_ur = (const float*)d_in[11];
    const float* W_out_ru = (const float*)d_in[12]; const float* b_out_ru = (const float*)d_in[13];
    const float* W_hcu = (const float*)d_in[14]; const float* b_hcu = (const float*)d_in[15];
    const float* W_hcr = (const float*)d_in[16]; const float* b_hcr = (const float*)d_in[17];
    const float* W_ocu = (const float*)d_in[18]; const float* b_ocu = (const float*)d_in[19];
    const float* W_ocr = (const float*)d_in[20]; const float* b_ocr = (const float*)d_in[21];
    const int* e_ur_src = (const int*)d_in[22];
    const int* e_ur_dst = (const int*)d_in[23];
    const int* e_ru_src = (const int*)d_in[24];
    const int* e_ru_dst = (const int*)d_in[25];
    const int* pos_u = (const int*)d_in[26];
    const int* pos_r = (const int*)d_in[27];
    const int* neg_u = (const int*)d_in[28];
    const int* neg_r = (const int*)d_in[29];
    float* out = (float*)d_out;

    __half* a_user = (__half*)sym(g_a_user);
    __half* a_repo = (__half*)sym(g_a_repo);
    __half* feat_u = (__half*)sym(g_feat_u);
    __half* feat_r = (__half*)sym(g_feat_r);
    float*  raw_u  = (float*)sym(g_raw_u);
    float*  raw_r  = (float*)sym(g_raw_r);
    __half* out_user = (__half*)sym(g_out_user);
    __half* out_repo = (__half*)sym(g_out_repo);
    float*  new_user = (float*)sym(g_new_user);
    float*  new_repo = (float*)sym(g_new_repo);
    int* cnt_u_out = (int*)sym(g_cnt_u_out);
    int* cnt_u_in  = (int*)sym(g_cnt_u_in);
    int* cnt_r_out = (int*)sym(g_cnt_r_out);
    int* cnt_r_in  = (int*)sym(g_cnt_r_in);
    float* rs_u_out = (float*)sym(g_rs_u_out);
    float* rs_u_in  = (float*)sym(g_rs_u_in);
    float* rs_r_out = (float*)sym(g_rs_r_out);
    float* rs_r_in  = (float*)sym(g_rs_r_in);
    int* rowptr_ur = (int*)sym(g_rowptr_ur);
    int* rowptr_ru = (int*)sym(g_rowptr_ru);
    int* cursor_ur = (int*)sym(g_cursor_ur);
    int* cursor_ru = (int*)sym(g_cursor_ru);
    int* col_ur = (int*)sym(g_col_ur);
    int* col_ru = (int*)sym(g_col_ru);
    int* part   = (int*)sym(g_part);
    float* invn_u = (float*)sym(g_invn_u);
    float* invn_r = (float*)sym(g_invn_r);
    __half* WCt_u1 = (__half*)sym(g_WCt_u1);
    __half* WCt_r1 = (__half*)sym(g_WCt_r1);
    float* bc_u1 = (float*)sym(g_bc_u1);
    float* bc_r1 = (float*)sym(g_bc_r1);
    __half* wc2t_u = (__half*)sym(g_wc2t_u);
    __half* wc2t_r = (__half*)sym(g_wc2t_r);

    const int T = 256;
    auto blocks = [](long n, int t) { return (int)((n + t - 1) / t); };

    cudaMemsetAsync(cnt_u_out, 0, N_USER * sizeof(int), 0);
    cudaMemsetAsync(cnt_u_in,  0, N_USER * sizeof(int), 0);
    cudaMemsetAsync(cnt_r_out, 0, N_REPO * sizeof(int), 0);
    cudaMemsetAsync(cnt_r_in,  0, N_REPO * sizeof(int), 0);

    k_tofp16<<<blocks((long)NU8 + NR8, T), T>>>(user_feat, repo_feat);
    k_pack2<<<blocks(2 * 128 * 96, T), T>>>(W_out_ur, W_ocu, W_out_ru, W_ocr);
    k_fold<<<blocks(2L * D_IN * 192 + 384, T), T>>>(W_ue, b_ue, W_hid_ur, W_hcu,
                                                    W_re, b_re, W_hid_ru, W_hcr);

    dim3 tb(128);
    auto grid = [](int M, int N) { return dim3(N / BN, (M + BM - 1) / BM); };

    // layer-1 fused GEMMs: Xh @ WCt^T + bc -> [feat fp16 | raw fp32]
    k_gemm_f16<<<grid(N_REPO, 192), tb>>>(a_repo, WCt_r1,
        feat_r, D_HID, raw_r, D_HID, D_HID, N_REPO, 192, D_IN, bc_r1);
    k_gemm_f16<<<grid(N_USER, 192), tb>>>(a_user, WCt_u1,
        feat_u, D_HID, raw_u, D_HID, D_HID, N_USER, 192, D_IN, bc_u1);

    // graph structure
    k_count_all<<<blocks(2L * NE, T), T>>>(e_ur_src, e_ur_dst, e_ru_src, e_ru_dst);
    k_rsqrt_all<<<blocks(2L * (N_USER + N_REPO), T), T>>>();
    int nb_r = (N_REPO + 1023) / 1024;
    int nb_u = (N_USER + 1023) / 1024;
    k_scan_block<<<nb_r, 1024>>>(cnt_r_in, rowptr_ur, part, N_REPO);
    k_scan_part<<<1, 128>>>(part, nb_r);
    k_scan_add<<<blocks(N_REPO, T), T>>>(rowptr_ur, cursor_ur, part, N_REPO);
    k_scan_block<<<nb_u, 1024>>>(cnt_u_in, rowptr_ru, part, N_USER);
    k_scan_part<<<1, 128>>>(part, nb_u);
    k_scan_add<<<blocks(N_USER, T), T>>>(rowptr_ru, cursor_ru, part, N_USER);
    k_fill_all<<<blocks(2L * NE, T), T>>>(e_ur_src, e_ur_dst, e_ru_src, e_ru_dst);

    // layer-1 SpMM + residual -> fp16 out
    k_spmm_out96<<<blocks(N_USER * 32L, T), T>>>(feat_r, rowptr_ru, col_ru, rs_r_out,
                                                 raw_u, rs_u_in, b_hcu, b_hid_ru,
                                                 out_user, N_USER);
    k_spmm_out96<<<blocks(N_REPO * 32L, T), T>>>(feat_u, rowptr_ur, col_ur, rs_u_out,
                                                 raw_r, rs_r_in, b_hcr, b_hid_ur,
                                                 out_repo, N_REPO);

    // layer-2 GEMMs (K=96)
    k_gemm_f16<<<grid(N_REPO, 128), tb>>>(out_repo, wc2t_r,
        feat_r, D_OUT, raw_r, D_OUT, D_OUT, N_REPO, 128, D_HID, nullptr);
    k_gemm_f16<<<grid(N_USER, 128), tb>>>(out_user, wc2t_u,
        feat_u, D_OUT, raw_u, D_OUT, D_OUT, N_USER, 128, D_HID, nullptr);

    // layer-2 SpMM + residual + norm (half-warp per row)
    k_spmm_out64_norm<<<blocks(N_USER * 16L, T), T>>>(feat_r, rowptr_ru, col_ru, rs_r_out,
                                                      raw_u, rs_u_in, b_ocu, b_out_ru,
                                                      new_user, invn_u, N_USER);
    k_spmm_out64_norm<<<blocks(N_REPO * 16L, T), T>>>(feat_u, rowptr_ur, col_ur, rs_u_out,
                                                      raw_r, rs_r_in, b_ocr, b_out_ur,
                                                      new_repo, invn_r, N_REPO);

    // cosine scores (half-warp per pair)
    k_score_all<<<blocks(2L * NEP * 16, T), T>>>(new_user, new_repo, invn_u, invn_r,
                                                 pos_u, pos_r, neg_u, neg_r, out);
}

// round 16
// speedup vs baseline: 1.1029x; 1.0086x over previous
#include <cuda_runtime.h>
#include <cuda_fp16.h>
#include <math.h>

// ---------------- problem constants ----------------
#define N_USER 50000
#define N_REPO 100000
#define NE     1000000
#define NEP    200000
#define D_IN   256
#define D_EMB  125
#define D_HID  96
#define D_OUT  64

// ---------------- scratch (device globals) ----------------
__device__ __align__(16) __half g_a_user[N_USER * D_IN];
__device__ __align__(16) __half g_a_repo[N_REPO * D_IN];
__device__ __align__(16) __half g_feat_u[N_USER * D_HID];
__device__ __align__(16) __half g_feat_r[N_REPO * D_HID];
__device__ float  g_raw_u [N_USER * D_HID];
__device__ float  g_raw_r [N_REPO * D_HID];
__device__ __align__(16) __half g_out_user[N_USER * D_HID];
__device__ __align__(16) __half g_out_repo[N_REPO * D_HID];
__device__ float  g_new_user[N_USER * D_OUT];
__device__ float  g_new_repo[N_REPO * D_OUT];

__device__ int   g_cnt_u_out[N_USER];
__device__ int   g_cnt_u_in [N_USER];
__device__ int   g_cnt_r_out[N_REPO];
__device__ int   g_cnt_r_in [N_REPO];
__device__ float g_rs_u_out[N_USER], g_rs_u_in[N_USER];
__device__ float g_rs_r_out[N_REPO], g_rs_r_in[N_REPO];

__device__ int g_rowptr_ur[N_REPO + 1];
__device__ int g_rowptr_ru[N_USER + 1];
__device__ int g_cursor_ur[N_REPO];
__device__ int g_cursor_ru[N_USER];
__device__ int g_col_ur[NE];
__device__ int g_col_ru[NE];
__device__ int g_part[128];

__device__ float g_invn_u[N_USER];
__device__ float g_invn_r[N_REPO];

__device__ __align__(16) __half g_WCt_u1[192 * D_IN];
__device__ __align__(16) __half g_WCt_r1[192 * D_IN];
__device__ float g_bc_u1[192];
__device__ float g_bc_r1[192];
__device__ __align__(16) __half g_wc2t_u[128 * D_HID];
__device__ __align__(16) __half g_wc2t_r[128 * D_HID];

// ---------------- preprocessing: fold + pack in one kernel ----------------
#define FOLD_PER (D_IN * 192)
#define PACK_PER (128 * 96)
__global__ void k_fold(const float* __restrict__ W_ue, const float* __restrict__ b_ue,
                       const float* __restrict__ W_hid_ur, const float* __restrict__ W_hcu,
                       const float* __restrict__ W_re, const float* __restrict__ b_re,
                       const float* __restrict__ W_hid_ru, const float* __restrict__ W_hcr,
                       const float* __restrict__ W_out_ur, const float* __restrict__ W_ocu,
                       const float* __restrict__ W_out_ru, const float* __restrict__ W_ocr) {
    int i = blockIdx.x * blockDim.x + threadIdx.x;
    if (i < 2 * FOLD_PER) {
        const float* We = (i < FOLD_PER) ? W_ue : W_re;
        const float* Wm = (i < FOLD_PER) ? W_hid_ur : W_hid_ru;
        const float* Wr = (i < FOLD_PER) ? W_hcu : W_hcr;
        __half* WCt = (i < FOLD_PER) ? g_WCt_u1 : g_WCt_r1;
        int j = (i < FOLD_PER) ? i : i - FOLD_PER;
        int n = j / D_IN, m = j % D_IN;
        const float* Wx = (n < 96) ? (Wm + n) : (Wr + n - 96);
        float a = 0.f;
        #pragma unroll 5
        for (int k = 0; k < D_EMB; k++) a += We[m * D_EMB + k] * Wx[k * 96];
        WCt[n * D_IN + m] = __float2half_rn(a);
        return;
    }
    i -= 2 * FOLD_PER;
    if (i < 384) {
        const float* be = (i < 192) ? b_ue : b_re;
        const float* Wm = (i < 192) ? W_hid_ur : W_hid_ru;
        const float* Wr = (i < 192) ? W_hcu : W_hcr;
        float* bc = (i < 192) ? g_bc_u1 : g_bc_r1;
        int n = i % 192;
        const float* Wx = (n < 96) ? (Wm + n) : (Wr + n - 96);
        float a = 0.f;
        for (int k = 0; k < D_EMB; k++) a += be[k] * Wx[k * 96];
        bc[n] = a;
        return;
    }
    i -= 384;
    if (i < 2 * PACK_PER) {
        int half_sel = i / PACK_PER;
        int j = i - half_sel * PACK_PER;
        int n = j / 96, k = j % 96;
        const float* Wa = half_sel ? W_out_ru : W_out_ur;
        const float* Wb = half_sel ? W_ocr    : W_ocu;
        float v = (n < 64) ? Wa[k * 64 + n] : Wb[k * 64 + (n - 64)];
        __half* dst = half_sel ? g_wc2t_r : g_wc2t_u;
        dst[n * 96 + k] = __float2half_rn(v);
    }
}
#define FOLD_TOTAL (2 * FOLD_PER + 384 + 2 * PACK_PER)

// fp32 -> fp16: 8 floats per thread
#define NU8 (N_USER * (D_IN / 8))
#define NR8 (N_REPO * (D_IN / 8))
__global__ void k_tofp16(const float* __restrict__ u, const float* __restrict__ r) {
    long i = blockIdx.x * (long)blockDim.x + threadIdx.x;
    const float4* src;
    uint4* dst;
    long j;
    if (i < NU8) { src = (const float4*)u; dst = (uint4*)g_a_user; j = i; }
    else if (i < NU8 + NR8) { src = (const float4*)r; dst = (uint4*)g_a_repo; j = i - NU8; }
    else return;
    float4 v0 = src[2 * j];
    float4 v1 = src[2 * j + 1];
    union { __half2 h[4]; uint4 q; } cv;
    cv.h[0] = __floats2half2_rn(v0.x, v0.y);
    cv.h[1] = __floats2half2_rn(v0.z, v0.w);
    cv.h[2] = __floats2half2_rn(v1.x, v1.y);
    cv.h[3] = __floats2half2_rn(v1.z, v1.w);
    dst[j] = cv.q;
}

__global__ void k_count_all(const int* __restrict__ ur_src, const int* __restrict__ ur_dst,
                            const int* __restrict__ ru_src, const int* __restrict__ ru_dst) {
    int i = blockIdx.x * blockDim.x + threadIdx.x;
    if (i < NE) {
        atomicAdd(&g_cnt_u_out[ur_src[i]], 1);
        atomicAdd(&g_cnt_r_in[ur_dst[i]], 1);
    } else if (i < 2 * NE) {
        int j = i - NE;
        atomicAdd(&g_cnt_r_out[ru_src[j]], 1);
        atomicAdd(&g_cnt_u_in[ru_dst[j]], 1);
    }
}

__global__ void k_rsqrt_all() {
    int i = blockIdx.x * blockDim.x + threadIdx.x;
    if (i < N_USER) { g_rs_u_out[i] = rsqrtf(fmaxf((float)g_cnt_u_out[i], 1.f)); return; }
    i -= N_USER;
    if (i < N_USER) { g_rs_u_in[i] = rsqrtf(fmaxf((float)g_cnt_u_in[i], 1.f)); return; }
    i -= N_USER;
    if (i < N_REPO) { g_rs_r_out[i] = rsqrtf(fmaxf((float)g_cnt_r_out[i], 1.f)); return; }
    i -= N_REPO;
    if (i < N_REPO) { g_rs_r_in[i] = rsqrtf(fmaxf((float)g_cnt_r_in[i], 1.f)); return; }
}

__global__ void k_scan_block(const int* __restrict__ cnt, int* rowptr, int* partial, int n) {
    __shared__ int sh[1024];
    int b = blockIdx.x, t = threadIdx.x;
    int i = b * 1024 + t;
    int v = (i < n) ? cnt[i] : 0;
    sh[t] = v;
    __syncthreads();
    for (int off = 1; off < 1024; off <<= 1) {
        int x = (t >= off) ? sh[t - off] : 0;
        __syncthreads();
        sh[t] += x;
        __syncthreads();
    }
    if (i < n) rowptr[i + 1] = sh[t];
    if (t == 1023) partial[b] = sh[1023];
}

__global__ void k_scan_part(int* partial, int nb) {
    __shared__ int sh[128];
    int t = threadIdx.x;
    int v = (t < nb) ? partial[t] : 0;
    sh[t] = v;
    __syncthreads();
    for (int off = 1; off < 128; off <<= 1) {
        int x = (t >= off) ? sh[t - off] : 0;
        __syncthreads();
        sh[t] += x;
        __syncthreads();
    }
    if (t < nb) partial[t] = sh[t] - v;
}

__global__ void k_scan_add(int* rowptr, int* cursor, const int* __restrict__ partial, int n) {
    int i = blockIdx.x * blockDim.x + threadIdx.x;
    if (i == 0) { rowptr[0] = 0; cursor[0] = 0; }
    if (i < n) {
        int v = rowptr[i + 1] + partial[i >> 10];
        rowptr[i + 1] = v;
        if (i + 1 < n) cursor[i + 1] = v;
    }
}

__global__ void k_fill_all(const int* __restrict__ ur_src, const int* __restrict__ ur_dst,
                           const int* __restrict__ ru_src, const int* __restrict__ ru_dst) {
    int i = blockIdx.x * blockDim.x + threadIdx.x;
    if (i < NE) {
        int p = atomicAdd(&g_cursor_ur[ur_dst[i]], 1);
        g_col_ur[p] = ur_src[i];
    } else if (i < 2 * NE) {
        int j = i - NE;
        int p = atomicAdd(&g_cursor_ru[ru_dst[j]], 1);
        g_col_ru[p] = ru_src[j];
    }
}

// ---------------- fp16 GEMM: 3-stage cp.async + ldmatrix + m16n8k16 ----------------
// 128 threads, 4 warps 2x2, warp tile 64x32; single barrier per tile
#define BM 128
#define BN 64
#define BK 32
#define APITCH 40
#define BPITCH 40
#define AHALVES (BM * APITCH)
#define BHALVES (BN * BPITCH)

__device__ __forceinline__ void mma_f16(float c[4],
                                        unsigned a0, unsigned a1, unsigned a2, unsigned a3,
                                        unsigned b0, unsigned b1) {
    asm volatile(
        "mma.sync.aligned.m16n8k16.row.col.f32.f16.f16.f32 "
        "{%0,%1,%2,%3}, {%4,%5,%6,%7}, {%8,%9}, {%0,%1,%2,%3};"
        : "+f"(c[0]), "+f"(c[1]), "+f"(c[2]), "+f"(c[3])
        : "r"(a0), "r"(a1), "r"(a2), "r"(a3), "r"(b0), "r"(b1));
}

__device__ __forceinline__ void ldsm_x4(unsigned& r0, unsigned& r1, unsigned& r2, unsigned& r3,
                                        unsigned addr) {
    asm volatile("ldmatrix.sync.aligned.m8n8.x4.shared.b16 {%0,%1,%2,%3}, [%4];"
                 : "=r"(r0), "=r"(r1), "=r"(r2), "=r"(r3) : "r"(addr));
}

__device__ __forceinline__ void cp_async16(unsigned dst, const void* src) {
    asm volatile("cp.async.cg.shared.global [%0], [%1], 16;" :: "r"(dst), "l"(src));
}
__device__ __forceinline__ void cp_commit() {
    asm volatile("cp.async.commit_group;");
}
template <int N>
__device__ __forceinline__ void cp_wait() {
    asm volatile("cp.async.wait_group %0;" :: "n"(N));
}

__global__ __launch_bounds__(128) void k_gemm_f16(
    const __half* __restrict__ A, const __half* __restrict__ Wt,
    __half* __restrict__ C1h, int ld1,
    float* __restrict__ C2, int ld2, int nsplit,
    int M, int N, int K,
    const float* __restrict__ bias)
{
    __shared__ __half As_s[3][AHALVES];
    __shared__ __half Bs_s[3][BHALVES];

    const int tid = threadIdx.x;
    const int warp = tid >> 5, lane = tid & 31;
    const int wm = (warp >> 1) * 64;
    const int wn = (warp & 1) * 32;
    const int m0 = blockIdx.y * BM;
    const int n0 = blockIdx.x * BN;
    const int r = lane >> 2, kc = lane & 3;

    float acc[4][4][4];
    #pragma unroll
    for (int a = 0; a < 4; a++)
        #pragma unroll
        for (int b = 0; b < 4; b++)
            #pragma unroll
            for (int c = 0; c < 4; c++) acc[a][b][c] = 0.f;

    const unsigned as0 = (unsigned)__cvta_generic_to_shared(&As_s[0][0]);
    const unsigned bs0 = (unsigned)__cvta_generic_to_shared(&Bs_s[0][0]);

    const int q = lane >> 3, lr = lane & 7;
    const unsigned a_lm = ((wm + (q & 1) * 8 + lr) * APITCH + (q >> 1) * 8) << 1;
    const unsigned b_lm = ((wn + (q >> 1) * 8 + lr) * BPITCH + (q & 1) * 8) << 1;

    const int a_row = tid >> 2, a_c = tid & 3;
    const int b_row = tid >> 2, b_c = tid & 3;

    const int T = K / BK;

    auto stage = [&](int t, int buf) {
        const int k0 = t * BK;
        const unsigned ab = as0 + buf * (AHALVES * 2);
        const unsigned bb = bs0 + buf * (BHALVES * 2);
        #pragma unroll
        for (int j = 0; j < 4; j++) {
            int row = a_row + j * 32;
            int m = m0 + row;
            if (m < M)
                cp_async16(ab + ((row * APITCH + a_c * 8) << 1),
                           A + (size_t)m * K + k0 + a_c * 8);
        }
        #pragma unroll
        for (int j = 0; j < 2; j++) {
            int row = b_row + j * 32;
            cp_async16(bb + ((row * BPITCH + b_c * 8) << 1),
                       Wt + (size_t)(n0 + row) * K + k0 + b_c * 8);
        }
        cp_commit();
    };

    // prologue: stage tiles 0 and 1
    stage(0, 0);
    if (T > 1) stage(1, 1);

    for (int t = 0; t < T; t++) {
        if (t + 1 < T) cp_wait<1>(); else cp_wait<0>();
        __syncthreads();   // single barrier per tile: orders compute(t-1) before stage into (t-1)%3

        if (t + 2 < T) stage(t + 2, (t + 2) % 3);

        const int buf = t % 3;
        const unsigned abuf = as0 + buf * (AHALVES * 2) + a_lm;
        const unsigned bbuf = bs0 + buf * (BHALVES * 2) + b_lm;
        #pragma unroll
        for (int g = 0; g < 2; g++) {
            unsigned af[4][4], bf[4][2];
            #pragma unroll
            for (int mt = 0; mt < 4; mt++)
                ldsm_x4(af[mt][0], af[mt][1], af[mt][2], af[mt][3],
                        abuf + ((mt * 16 * APITCH + g * 16) << 1));
            #pragma unroll
            for (int np = 0; np < 2; np++) {
                unsigned r0, r1, r2, r3;
                ldsm_x4(r0, r1, r2, r3, bbuf + ((np * 16 * BPITCH + g * 16) << 1));
                bf[2 * np][0] = r0;  bf[2 * np][1] = r1;
                bf[2 * np + 1][0] = r2;  bf[2 * np + 1][1] = r3;
            }
            #pragma unroll
            for (int mt = 0; mt < 4; mt++)
                #pragma unroll
                for (int nt = 0; nt < 4; nt++)
                    mma_f16(acc[mt][nt], af[mt][0], af[mt][1], af[mt][2], af[mt][3],
                            bf[nt][0], bf[nt][1]);
        }
        // no trailing barrier: next iteration's leading barrier provides the WAR guard
    }

    #pragma unroll
    for (int mt = 0; mt < 4; mt++) {
        #pragma unroll
        for (int i2 = 0; i2 < 2; i2++) {
            int m = m0 + wm + mt * 16 + r + i2 * 8;
            if (m >= M) continue;
            #pragma unroll
            for (int nt = 0; nt < 4; nt++) {
                int n = n0 + wn + nt * 8 + kc * 2;
                float v0 = acc[mt][nt][i2 * 2 + 0];
                float v1 = acc[mt][nt][i2 * 2 + 1];
                if (bias) { v0 += bias[n]; v1 += bias[n + 1]; }
                if (n < nsplit) {
                    __half2 h = __floats2half2_rn(v0, v1);
                    *(__half2*)(C1h + (size_t)m * ld1 + n) = h;
                } else {
                    *(float2*)(C2 + (size_t)m * ld2 + n - nsplit) = make_float2(v0, v1);
                }
            }
        }
    }
}

// ---------------- fused SpMM + residual epilogue (layer 1: fp16 out) ----------------
__global__ void k_spmm_out96(const __half* __restrict__ feat, const int* __restrict__ rowptr,
                             const int* __restrict__ col, const float* __restrict__ rs_src,
                             const float* __restrict__ raw, const float* __restrict__ rs_in,
                             const float* __restrict__ b1, const float* __restrict__ b2,
                             __half* __restrict__ out, int n_rows) {
    int w = (blockIdx.x * blockDim.x + threadIdx.x) >> 5;
    int lane = threadIdx.x & 31;
    if (w >= n_rows) return;
    int s = rowptr[w], e = rowptr[w + 1];
    bool act = lane < 24;
    int d = lane * 4;
    float4 a0 = make_float4(0.f, 0.f, 0.f, 0.f);
    float4 a1 = make_float4(0.f, 0.f, 0.f, 0.f);
    int i = s;
    for (; i + 3 < e; i += 4) {
        int c0 = col[i], c1 = col[i + 1], c2 = col[i + 2], c3 = col[i + 3];
        float s0 = rs_src[c0], s1 = rs_src[c1], s2 = rs_src[c2], s3 = rs_src[c3];
        if (act) {
            uint2 q0 = *(const uint2*)(feat + (size_t)c0 * 96 + d);
            uint2 q1 = *(const uint2*)(feat + (size_t)c1 * 96 + d);
            uint2 q2 = *(const uint2*)(feat + (size_t)c2 * 96 + d);
            uint2 q3 = *(const uint2*)(feat + (size_t)c3 * 96 + d);
            float2 f;
            f = __half22float2(*(__half2*)&q0.x); a0.x += f.x * s0; a0.y += f.y * s0;
            f = __half22float2(*(__half2*)&q0.y); a0.z += f.x * s0; a0.w += f.y * s0;
            f = __half22float2(*(__half2*)&q1.x); a1.x += f.x * s1; a1.y += f.y * s1;
            f = __half22float2(*(__half2*)&q1.y); a1.z += f.x * s1; a1.w += f.y * s1;
            f = __half22float2(*(__half2*)&q2.x); a0.x += f.x * s2; a0.y += f.y * s2;
            f = __half22float2(*(__half2*)&q2.y); a0.z += f.x * s2; a0.w += f.y * s2;
            f = __half22float2(*(__half2*)&q3.x); a1.x += f.x * s3; a1.y += f.y * s3;
            f = __half22float2(*(__half2*)&q3.y); a1.z += f.x * s3; a1.w += f.y * s3;
        }
    }
    for (; i < e; i++) {
        int c0 = col[i];
        float s0 = rs_src[c0];
        if (act) {
            uint2 q0 = *(const uint2*)(feat + (size_t)c0 * 96 + d);
            float2 f;
            f = __half22float2(*(__half2*)&q0.x); a0.x += f.x * s0; a0.y += f.y * s0;
            f = __half22float2(*(__half2*)&q0.y); a0.z += f.x * s0; a0.w += f.y * s0;
        }
    }
    if (act) {
        float sc = rs_in[w];
        float4 r4 = *(const float4*)(raw + (size_t)w * 96 + d);
        float ox = fmaxf(r4.x + b1[d + 0] + b2[d + 0] + (a0.x + a1.x) * sc, 0.f);
        float oy = fmaxf(r4.y + b1[d + 1] + b2[d + 1] + (a0.y + a1.y) * sc, 0.f);
        float oz = fmaxf(r4.z + b1[d + 2] + b2[d + 2] + (a0.z + a1.z) * sc, 0.f);
        float ow = fmaxf(r4.w + b1[d + 3] + b2[d + 3] + (a0.w + a1.w) * sc, 0.f);
        union { __half2 h[2]; uint2 q; } cv;
        cv.h[0] = __floats2half2_rn(ox, oy);
        cv.h[1] = __floats2half2_rn(oz, ow);
        *(uint2*)(out + (size_t)w * 96 + d) = cv.q;
    }
}

// layer 2 (D=64): HALF-WARP per row (16 lanes), fp32 out + fused inverse-norm
__global__ void k_spmm_out64_norm(const __half* __restrict__ feat, const int* __restrict__ rowptr,
                                  const int* __restrict__ col, const float* __restrict__ rs_src,
                                  const float* __restrict__ raw, const float* __restrict__ rs_in,
                                  const float* __restrict__ b1, const float* __restrict__ b2,
                                  float* __restrict__ out, float* __restrict__ invn, int n_rows) {
    int gt = blockIdx.x * blockDim.x + threadIdx.x;
    int w = gt >> 4;
    int lane = threadIdx.x & 15;
    if (w >= n_rows) return;
    int s = rowptr[w], e = rowptr[w + 1];
    int d = lane * 4;
    float4 a0 = make_float4(0.f, 0.f, 0.f, 0.f);
    float4 a1 = make_float4(0.f, 0.f, 0.f, 0.f);
    int i = s;
    for (; i + 3 < e; i += 4) {
        int c0 = col[i], c1 = col[i + 1], c2 = col[i + 2], c3 = col[i + 3];
        float s0 = rs_src[c0], s1 = rs_src[c1], s2 = rs_src[c2], s3 = rs_src[c3];
        uint2 q0 = *(const uint2*)(feat + (size_t)c0 * 64 + d);
        uint2 q1 = *(const uint2*)(feat + (size_t)c1 * 64 + d);
        uint2 q2 = *(const uint2*)(feat + (size_t)c2 * 64 + d);
        uint2 q3 = *(const uint2*)(feat + (size_t)c3 * 64 + d);
        float2 f;
        f = __half22float2(*(__half2*)&q0.x); a0.x += f.x * s0; a0.y += f.y * s0;
        f = __half22float2(*(__half2*)&q0.y); a0.z += f.x * s0; a0.w += f.y * s0;
        f = __half22float2(*(__half2*)&q1.x); a1.x += f.x * s1; a1.y += f.y * s1;
        f = __half22float2(*(__half2*)&q1.y); a1.z += f.x * s1; a1.w += f.y * s1;
        f = __half22float2(*(__half2*)&q2.x); a0.x += f.x * s2; a0.y += f.y * s2;
        f = __half22float2(*(__half2*)&q2.y); a0.z += f.x * s2; a0.w += f.y * s2;
        f = __half22float2(*(__half2*)&q3.x); a1.x += f.x * s3; a1.y += f.y * s3;
        f = __half22float2(*(__half2*)&q3.y); a1.z += f.x * s3; a1.w += f.y * s3;
    }
    for (; i < e; i++) {
        int c0 = col[i];
        float s0 = rs_src[c0];
        uint2 q0 = *(const uint2*)(feat + (size_t)c0 * 64 + d);
        float2 f;
        f = __half22float2(*(__half2*)&q0.x); a0.x += f.x * s0; a0.y += f.y * s0;
        f = __half22float2(*(__half2*)&q0.y); a0.z += f.x * s0; a0.w += f.y * s0;
    }
    float sq;
    {
        float sc = rs_in[w];
        float4 r4 = *(const float4*)(raw + (size_t)w * 64 + d);
        float4 o;
        o.x = fmaxf(r4.x + b1[d + 0] + b2[d + 0] + (a0.x + a1.x) * sc, 0.f);
        o.y = fmaxf(r4.y + b1[d + 1] + b2[d + 1] + (a0.y + a1.y) * sc, 0.f);
        o.z = fmaxf(r4.z + b1[d + 2] + b2[d + 2] + (a0.z + a1.z) * sc, 0.f);
        o.w = fmaxf(r4.w + b1[d + 3] + b2[d + 3] + (a0.w + a1.w) * sc, 0.f);
        *(float4*)(out + (size_t)w * 64 + d) = o;
        sq = o.x * o.x + o.y * o.y + o.z * o.z + o.w * o.w;
    }
    #pragma unroll
    for (int off = 8; off; off >>= 1) sq += __shfl_xor_sync(0xffffffffu, sq, off);
    if (lane == 0) invn[w] = 1.0f / fmaxf(sqrtf(sq), 1e-12f);
}

// ---------------- score: half-warp per pair, float4 loads ----------------
__global__ void k_score_all(const float* __restrict__ hu, const float* __restrict__ hr,
                            const float* __restrict__ invn_u, const float* __restrict__ invn_r,
                            const int* __restrict__ pos_u, const int* __restrict__ pos_r,
                            const int* __restrict__ neg_u, const int* __restrict__ neg_r,
                            float* __restrict__ out) {
    int gt = blockIdx.x * blockDim.x + threadIdx.x;
    int w = gt >> 4;
    int lane = threadIdx.x & 15;
    if (w >= 2 * NEP) return;
    int u, r;
    if (w < NEP) { u = pos_u[w]; r = pos_r[w]; }
    else         { u = neg_u[w - NEP]; r = neg_r[w - NEP]; }
    float4 a4 = *(const float4*)(hu + (size_t)u * D_OUT + lane * 4);
    float4 b4 = *(const float4*)(hr + (size_t)r * D_OUT + lane * 4);
    float s = a4.x * b4.x + a4.y * b4.y + a4.z * b4.z + a4.w * b4.w;
    #pragma unroll
    for (int off = 8; off; off >>= 1) s += __shfl_xor_sync(0xffffffffu, s, off);
    if (lane == 0) out[w] = s * invn_u[u] * invn_r[r];
}

// ---------------- host ----------------
static inline void* sym(const void* s) {
    void* p = nullptr;
    cudaGetSymbolAddress(&p, s);
    return p;
}

extern "C" void kernel_launch(void* const* d_in, const int* in_sizes, int n_in,
                              void* d_out, int out_size) {
    const float* user_feat = (const float*)d_in[0];
    const float* repo_feat = (const float*)d_in[1];
    const float* W_ue = (const float*)d_in[2];   const float* b_ue = (const float*)d_in[3];
    const float* W_re = (const float*)d_in[4];   const float* b_re = (const float*)d_in[5];
    const float* W_hid_ur = (const float*)d_in[6];  const float* b_hid_ur = (const float*)d_in[7];
    const float* W_hid_ru = (const float*)d_in[8];  const float* b_hid_ru = (const float*)d_in[9];
    const float* W_out_ur = (const float*)d_in[10]; const float* b_out_ur = (const float*)d_in[11];
    const float* W_out_ru = (const float*)d_in[12]; const float* b_out_ru = (const float*)d_in[13];
    const float* W_hcu = (const float*)d_in[14]; const float* b_hcu = (const float*)d_in[15];
    const float* W_hcr = (const float*)d_in[16]; const float* b_hcr = (const float*)d_in[17];
    const float* W_ocu = (const float*)d_in[18]; const float* b_ocu = (const float*)d_in[19];
    const float* W_ocr = (const float*)d_in[20]; const float* b_ocr = (const float*)d_in[21];
    const int* e_ur_src = (const int*)d_in[22];
    const int* e_ur_dst = (const int*)d_in[23];
    const int* e_ru_src = (const int*)d_in[24];
    const int* e_ru_dst = (const int*)d_in[25];
    const int* pos_u = (const int*)d_in[26];
    const int* pos_r = (const int*)d_in[27];
    const int* neg_u = (const int*)d_in[28];
    const int* neg_r = (const int*)d_in[29];
    float* out = (float*)d_out;

    __half* a_user = (__half*)sym(g_a_user);
    __half* a_repo = (__half*)sym(g_a_repo);
    __half* feat_u = (__half*)sym(g_feat_u);
    __half* feat_r = (__half*)sym(g_feat_r);
    float*  raw_u  = (float*)sym(g_raw_u);
    float*  raw_r  = (float*)sym(g_raw_r);
    __half* out_user = (__half*)sym(g_out_user);
    __half* out_repo = (__half*)sym(g_out_repo);
    float*  new_user = (float*)sym(g_new_user);
    float*  new_repo = (float*)sym(g_new_repo);
    int* cnt_u_out = (int*)sym(g_cnt_u_out);
    int* cnt_u_in  = (int*)sym(g_cnt_u_in);
    int* cnt_r_out = (int*)sym(g_cnt_r_out);
    int* cnt_r_in  = (int*)sym(g_cnt_r_in);
    float* rs_u_out = (float*)sym(g_rs_u_out);
    float* rs_u_in  = (float*)sym(g_rs_u_in);
    float* rs_r_out = (float*)sym(g_rs_r_out);
    float* rs_r_in  = (float*)sym(g_rs_r_in);
    int* rowptr_ur = (int*)sym(g_rowptr_ur);
    int* rowptr_ru = (int*)sym(g_rowptr_ru);
    int* cursor_ur = (int*)sym(g_cursor_ur);
    int* cursor_ru = (int*)sym(g_cursor_ru);
    int* col_ur = (int*)sym(g_col_ur);
    int* col_ru = (int*)sym(g_col_ru);
    int* part   = (int*)sym(g_part);
    float* invn_u = (float*)sym(g_invn_u);
    float* invn_r = (float*)sym(g_invn_r);
    __half* WCt_u1 = (__half*)sym(g_WCt_u1);
    __half* WCt_r1 = (__half*)sym(g_WCt_r1);
    float* bc_u1 = (float*)sym(g_bc_u1);
    float* bc_r1 = (float*)sym(g_bc_r1);
    __half* wc2t_u = (__half*)sym(g_wc2t_u);
    __half* wc2t_r = (__half*)sym(g_wc2t_r);

    const int T = 256;
    auto blocks = [](long n, int t) { return (int)((n + t - 1) / t); };

    cudaMemsetAsync(cnt_u_out, 0, N_USER * sizeof(int), 0);
    cudaMemsetAsync(cnt_u_in,  0, N_USER * sizeof(int), 0);
    cudaMemsetAsync(cnt_r_out, 0, N_REPO * sizeof(int), 0);
    cudaMemsetAsync(cnt_r_in,  0, N_REPO * sizeof(int), 0);

    k_tofp16<<<blocks((long)NU8 + NR8, T), T>>>(user_feat, repo_feat);
    k_fold<<<blocks(FOLD_TOTAL, T), T>>>(W_ue, b_ue, W_hid_ur, W_hcu,
                                         W_re, b_re, W_hid_ru, W_hcr,
                                         W_out_ur, W_ocu, W_out_ru, W_ocr);

    dim3 tb(128);
    auto grid = [](int M, int N) { return dim3(N / BN, (M + BM - 1) / BM); };

    // layer-1 fused GEMMs: Xh @ WCt^T + bc -> [feat fp16 | raw fp32]
    k_gemm_f16<<<grid(N_REPO, 192), tb>>>(a_repo, WCt_r1,
        feat_r, D_HID, raw_r, D_HID, D_HID, N_REPO, 192, D_IN, bc_r1);
    k_gemm_f16<<<grid(N_USER, 192), tb>>>(a_user, WCt_u1,
        feat_u, D_HID, raw_u, D_HID, D_HID, N_USER, 192, D_IN, bc_u1);

    // graph structure
    k_count_all<<<blocks(2L * NE, T), T>>>(e_ur_src, e_ur_dst, e_ru_src, e_ru_dst);
    k_rsqrt_all<<<blocks(2L * (N_USER + N_REPO), T), T>>>();
    int nb_r = (N_REPO + 1023) / 1024;
    int nb_u = (N_USER + 1023) / 1024;
    k_scan_block<<<nb_r, 1024>>>(cnt_r_in, rowptr_ur, part, N_REPO);
    k_scan_part<<<1, 128>>>(part, nb_r);
    k_scan_add<<<blocks(N_REPO, T), T>>>(rowptr_ur, cursor_ur, part, N_REPO);
    k_scan_block<<<nb_u, 1024>>>(cnt_u_in, rowptr_ru, part, N_USER);
    k_scan_part<<<1, 128>>>(part, nb_u);
    k_scan_add<<<blocks(N_USER, T), T>>>(rowptr_ru, cursor_ru, part, N_USER);
    k_fill_all<<<blocks(2L * NE, T), T>>>(e_ur_src, e_ur_dst, e_ru_src, e_ru_dst);

    // layer-1 SpMM + residual -> fp16 out
    k_spmm_out96<<<blocks(N_USER * 32L, T), T>>>(feat_r, rowptr_ru, col_ru, rs_r_out,
                                                 raw_u, rs_u_in, b_hcu, b_hid_ru,
                                                 out_user, N_USER);
    k_spmm_out96<<<blocks(N_REPO * 32L, T), T>>>(feat_u, rowptr_ur, col_ur, rs_u_out,
                                                 raw_r, rs_r_in, b_hcr, b_hid_ur,
                                                 out_repo, N_REPO);

    // layer-2 GEMMs (K=96)
    k_gemm_f16<<<grid(N_REPO, 128), tb>>>(out_repo, wc2t_r,
        feat_r, D_OUT, raw_r, D_OUT, D_OUT, N_REPO, 128, D_HID, nullptr);
    k_gemm_f16<<<grid(N_USER, 128), tb>>>(out_user, wc2t_u,
        feat_u, D_OUT, raw_u, D_OUT, D_OUT, N_USER, 128, D_HID, nullptr);

    // layer-2 SpMM + residual + norm (half-warp per row)
    k_spmm_out64_norm<<<blocks(N_USER * 16L, T), T>>>(feat_r, rowptr_ru, col_ru, rs_r_out,
                                                      raw_u, rs_u_in, b_ocu, b_out_ru,
                                                      new_user, invn_u, N_USER);
    k_spmm_out64_norm<<<blocks(N_REPO * 16L, T), T>>>(feat_u, rowptr_ur, col_ur, rs_u_out,
                                                      raw_r, rs_r_in, b_ocr, b_out_ur,
                                                      new_repo, invn_r, N_REPO);

    // cosine scores (half-warp per pair)
    k_score_all<<<blocks(2L * NEP * 16, T), T>>>(new_user, new_repo, invn_u, invn_r,
                                                 pos_u, pos_r, neg_u, neg_r, out);
}

// round 17
// speedup vs baseline: 1.1483x; 1.0412x over previous
#include <cuda_runtime.h>
#include <cuda_fp16.h>
#include <math.h>

// ---------------- problem constants ----------------
#define N_USER 50000
#define N_REPO 100000
#define NE     1000000
#define NEP    200000
#define D_IN   256
#define D_EMB  125
#define D_HID  96
#define D_OUT  64

// ---------------- scratch (device globals) ----------------
__device__ __align__(16) __half g_a_user[N_USER * D_IN];
__device__ __align__(16) __half g_a_repo[N_REPO * D_IN];
__device__ __align__(16) __half g_feat_u[N_USER * D_HID];
__device__ __align__(16) __half g_feat_r[N_REPO * D_HID];
__device__ float  g_raw_u [N_USER * D_HID];
__device__ float  g_raw_r [N_REPO * D_HID];
__device__ __align__(16) __half g_out_user[N_USER * D_HID];
__device__ __align__(16) __half g_out_repo[N_REPO * D_HID];
__device__ float  g_new_user[N_USER * D_OUT];
__device__ float  g_new_repo[N_REPO * D_OUT];

__device__ int   g_cnt_u_out[N_USER];
__device__ int   g_cnt_u_in [N_USER];
__device__ int   g_cnt_r_out[N_REPO];
__device__ int   g_cnt_r_in [N_REPO];
__device__ float g_rs_u_out[N_USER], g_rs_u_in[N_USER];
__device__ float g_rs_r_out[N_REPO], g_rs_r_in[N_REPO];

__device__ int g_rowptr_ur[N_REPO + 1];
__device__ int g_rowptr_ru[N_USER + 1];
__device__ int g_cursor_ur[N_REPO];
__device__ int g_cursor_ru[N_USER];
__device__ int g_col_ur[NE];
__device__ int g_col_ru[NE];
__device__ int g_part[128];

__device__ float g_invn_u[N_USER];
__device__ float g_invn_r[N_REPO];

__device__ __align__(16) __half g_WCt_u1[192 * D_IN];
__device__ __align__(16) __half g_WCt_r1[192 * D_IN];
__device__ float g_bc_u1[192];
__device__ float g_bc_r1[192];
__device__ __align__(16) __half g_wc2t_u[128 * D_HID];
__device__ __align__(16) __half g_wc2t_r[128 * D_HID];

// ---------------- preprocessing: fold + pack in one kernel ----------------
#define FOLD_PER (D_IN * 192)
#define PACK_PER (128 * 96)
__global__ void k_fold(const float* __restrict__ W_ue, const float* __restrict__ b_ue,
                       const float* __restrict__ W_hid_ur, const float* __restrict__ W_hcu,
                       const float* __restrict__ W_re, const float* __restrict__ b_re,
                       const float* __restrict__ W_hid_ru, const float* __restrict__ W_hcr,
                       const float* __restrict__ W_out_ur, const float* __restrict__ W_ocu,
                       const float* __restrict__ W_out_ru, const float* __restrict__ W_ocr) {
    int i = blockIdx.x * blockDim.x + threadIdx.x;
    if (i < 2 * FOLD_PER) {
        const float* We = (i < FOLD_PER) ? W_ue : W_re;
        const float* Wm = (i < FOLD_PER) ? W_hid_ur : W_hid_ru;
        const float* Wr = (i < FOLD_PER) ? W_hcu : W_hcr;
        __half* WCt = (i < FOLD_PER) ? g_WCt_u1 : g_WCt_r1;
        int j = (i < FOLD_PER) ? i : i - FOLD_PER;
        int n = j / D_IN, m = j % D_IN;
        const float* Wx = (n < 96) ? (Wm + n) : (Wr + n - 96);
        float a = 0.f;
        #pragma unroll 5
        for (int k = 0; k < D_EMB; k++) a += We[m * D_EMB + k] * Wx[k * 96];
        WCt[n * D_IN + m] = __float2half_rn(a);
        return;
    }
    i -= 2 * FOLD_PER;
    if (i < 384) {
        const float* be = (i < 192) ? b_ue : b_re;
        const float* Wm = (i < 192) ? W_hid_ur : W_hid_ru;
        const float* Wr = (i < 192) ? W_hcu : W_hcr;
        float* bc = (i < 192) ? g_bc_u1 : g_bc_r1;
        int n = i % 192;
        const float* Wx = (n < 96) ? (Wm + n) : (Wr + n - 96);
        float a = 0.f;
        for (int k = 0; k < D_EMB; k++) a += be[k] * Wx[k * 96];
        bc[n] = a;
        return;
    }
    i -= 384;
    if (i < 2 * PACK_PER) {
        int half_sel = i / PACK_PER;
        int j = i - half_sel * PACK_PER;
        int n = j / 96, k = j % 96;
        const float* Wa = half_sel ? W_out_ru : W_out_ur;
        const float* Wb = half_sel ? W_ocr    : W_ocu;
        float v = (n < 64) ? Wa[k * 64 + n] : Wb[k * 64 + (n - 64)];
        __half* dst = half_sel ? g_wc2t_r : g_wc2t_u;
        dst[n * 96 + k] = __float2half_rn(v);
    }
}
#define FOLD_TOTAL (2 * FOLD_PER + 384 + 2 * PACK_PER)

// fp32 -> fp16: 8 floats per thread
#define NU8 (N_USER * (D_IN / 8))
#define NR8 (N_REPO * (D_IN / 8))
__global__ void k_tofp16(const float* __restrict__ u, const float* __restrict__ r) {
    long i = blockIdx.x * (long)blockDim.x + threadIdx.x;
    const float4* src;
    uint4* dst;
    long j;
    if (i < NU8) { src = (const float4*)u; dst = (uint4*)g_a_user; j = i; }
    else if (i < NU8 + NR8) { src = (const float4*)r; dst = (uint4*)g_a_repo; j = i - NU8; }
    else return;
    float4 v0 = src[2 * j];
    float4 v1 = src[2 * j + 1];
    union { __half2 h[4]; uint4 q; } cv;
    cv.h[0] = __floats2half2_rn(v0.x, v0.y);
    cv.h[1] = __floats2half2_rn(v0.z, v0.w);
    cv.h[2] = __floats2half2_rn(v1.x, v1.y);
    cv.h[3] = __floats2half2_rn(v1.z, v1.w);
    dst[j] = cv.q;
}

__global__ void k_count_all(const int* __restrict__ ur_src, const int* __restrict__ ur_dst,
                            const int* __restrict__ ru_src, const int* __restrict__ ru_dst) {
    int i = blockIdx.x * blockDim.x + threadIdx.x;
    if (i < NE) {
        atomicAdd(&g_cnt_u_out[ur_src[i]], 1);
        atomicAdd(&g_cnt_r_in[ur_dst[i]], 1);
    } else if (i < 2 * NE) {
        int j = i - NE;
        atomicAdd(&g_cnt_r_out[ru_src[j]], 1);
        atomicAdd(&g_cnt_u_in[ru_dst[j]], 1);
    }
}

__global__ void k_rsqrt_all() {
    int i = blockIdx.x * blockDim.x + threadIdx.x;
    if (i < N_USER) { g_rs_u_out[i] = rsqrtf(fmaxf((float)g_cnt_u_out[i], 1.f)); return; }
    i -= N_USER;
    if (i < N_USER) { g_rs_u_in[i] = rsqrtf(fmaxf((float)g_cnt_u_in[i], 1.f)); return; }
    i -= N_USER;
    if (i < N_REPO) { g_rs_r_out[i] = rsqrtf(fmaxf((float)g_cnt_r_out[i], 1.f)); return; }
    i -= N_REPO;
    if (i < N_REPO) { g_rs_r_in[i] = rsqrtf(fmaxf((float)g_cnt_r_in[i], 1.f)); return; }
}

__global__ void k_scan_block(const int* __restrict__ cnt, int* rowptr, int* partial, int n) {
    __shared__ int sh[1024];
    int b = blockIdx.x, t = threadIdx.x;
    int i = b * 1024 + t;
    int v = (i < n) ? cnt[i] : 0;
    sh[t] = v;
    __syncthreads();
    for (int off = 1; off < 1024; off <<= 1) {
        int x = (t >= off) ? sh[t - off] : 0;
        __syncthreads();
        sh[t] += x;
        __syncthreads();
    }
    if (i < n) rowptr[i + 1] = sh[t];
    if (t == 1023) partial[b] = sh[1023];
}

__global__ void k_scan_part(int* partial, int nb) {
    __shared__ int sh[128];
    int t = threadIdx.x;
    int v = (t < nb) ? partial[t] : 0;
    sh[t] = v;
    __syncthreads();
    for (int off = 1; off < 128; off <<= 1) {
        int x = (t >= off) ? sh[t - off] : 0;
        __syncthreads();
        sh[t] += x;
        __syncthreads();
    }
    if (t < nb) partial[t] = sh[t] - v;
}

__global__ void k_scan_add(int* rowptr, int* cursor, const int* __restrict__ partial, int n) {
    int i = blockIdx.x * blockDim.x + threadIdx.x;
    if (i == 0) { rowptr[0] = 0; cursor[0] = 0; }
    if (i < n) {
        int v = rowptr[i + 1] + partial[i >> 10];
        rowptr[i + 1] = v;
        if (i + 1 < n) cursor[i + 1] = v;
    }
}

__global__ void k_fill_all(const int* __restrict__ ur_src, const int* __restrict__ ur_dst,
                           const int* __restrict__ ru_src, const int* __restrict__ ru_dst) {
    int i = blockIdx.x * blockDim.x + threadIdx.x;
    if (i < NE) {
        int p = atomicAdd(&g_cursor_ur[ur_dst[i]], 1);
        g_col_ur[p] = ur_src[i];
    } else if (i < 2 * NE) {
        int j = i - NE;
        int p = atomicAdd(&g_cursor_ru[ru_dst[j]], 1);
        g_col_ru[p] = ru_src[j];
    }
}

// ---------------- fp16 GEMM: 3-stage cp.async + ldmatrix + m16n8k16 ----------------
#define BM 128
#define BN 64
#define BK 32
#define APITCH 40
#define BPITCH 40
#define AHALVES (BM * APITCH)
#define BHALVES (BN * BPITCH)

__device__ __forceinline__ void mma_f16(float c[4],
                                        unsigned a0, unsigned a1, unsigned a2, unsigned a3,
                                        unsigned b0, unsigned b1) {
    asm volatile(
        "mma.sync.aligned.m16n8k16.row.col.f32.f16.f16.f32 "
        "{%0,%1,%2,%3}, {%4,%5,%6,%7}, {%8,%9}, {%0,%1,%2,%3};"
        : "+f"(c[0]), "+f"(c[1]), "+f"(c[2]), "+f"(c[3])
        : "r"(a0), "r"(a1), "r"(a2), "r"(a3), "r"(b0), "r"(b1));
}

__device__ __forceinline__ void ldsm_x4(unsigned& r0, unsigned& r1, unsigned& r2, unsigned& r3,
                                        unsigned addr) {
    asm volatile("ldmatrix.sync.aligned.m8n8.x4.shared.b16 {%0,%1,%2,%3}, [%4];"
                 : "=r"(r0), "=r"(r1), "=r"(r2), "=r"(r3) : "r"(addr));
}

__device__ __forceinline__ void cp_async16(unsigned dst, const void* src) {
    asm volatile("cp.async.cg.shared.global [%0], [%1], 16;" :: "r"(dst), "l"(src));
}
__device__ __forceinline__ void cp_commit() {
    asm volatile("cp.async.commit_group;");
}
template <int N>
__device__ __forceinline__ void cp_wait() {
    asm volatile("cp.async.wait_group %0;" :: "n"(N));
}

__global__ __launch_bounds__(128) void k_gemm_f16(
    const __half* __restrict__ A, const __half* __restrict__ Wt,
    __half* __restrict__ C1h, int ld1,
    float* __restrict__ C2, int ld2, int nsplit,
    int M, int N, int K,
    const float* __restrict__ bias)
{
    __shared__ __half As_s[3][AHALVES];
    __shared__ __half Bs_s[3][BHALVES];

    const int tid = threadIdx.x;
    const int warp = tid >> 5, lane = tid & 31;
    const int wm = (warp >> 1) * 64;
    const int wn = (warp & 1) * 32;
    const int m0 = blockIdx.y * BM;
    const int n0 = blockIdx.x * BN;
    const int r = lane >> 2, kc = lane & 3;

    float acc[4][4][4];
    #pragma unroll
    for (int a = 0; a < 4; a++)
        #pragma unroll
        for (int b = 0; b < 4; b++)
            #pragma unroll
            for (int c = 0; c < 4; c++) acc[a][b][c] = 0.f;

    const unsigned as0 = (unsigned)__cvta_generic_to_shared(&As_s[0][0]);
    const unsigned bs0 = (unsigned)__cvta_generic_to_shared(&Bs_s[0][0]);

    const int q = lane >> 3, lr = lane & 7;
    const unsigned a_lm = ((wm + (q & 1) * 8 + lr) * APITCH + (q >> 1) * 8) << 1;
    const unsigned b_lm = ((wn + (q >> 1) * 8 + lr) * BPITCH + (q & 1) * 8) << 1;

    const int a_row = tid >> 2, a_c = tid & 3;
    const int b_row = tid >> 2, b_c = tid & 3;

    const int T = K / BK;

    auto stage = [&](int t, int buf) {
        const int k0 = t * BK;
        const unsigned ab = as0 + buf * (AHALVES * 2);
        const unsigned bb = bs0 + buf * (BHALVES * 2);
        #pragma unroll
        for (int j = 0; j < 4; j++) {
            int row = a_row + j * 32;
            int m = m0 + row;
            if (m < M)
                cp_async16(ab + ((row * APITCH + a_c * 8) << 1),
                           A + (size_t)m * K + k0 + a_c * 8);
        }
        #pragma unroll
        for (int j = 0; j < 2; j++) {
            int row = b_row + j * 32;
            cp_async16(bb + ((row * BPITCH + b_c * 8) << 1),
                       Wt + (size_t)(n0 + row) * K + k0 + b_c * 8);
        }
        cp_commit();
    };

    stage(0, 0);
    if (T > 1) stage(1, 1);

    for (int t = 0; t < T; t++) {
        if (t + 1 < T) cp_wait<1>(); else cp_wait<0>();
        __syncthreads();

        if (t + 2 < T) stage(t + 2, (t + 2) % 3);

        const int buf = t % 3;
        const unsigned abuf = as0 + buf * (AHALVES * 2) + a_lm;
        const unsigned bbuf = bs0 + buf * (BHALVES * 2) + b_lm;
        #pragma unroll
        for (int g = 0; g < 2; g++) {
            unsigned af[4][4], bf[4][2];
            #pragma unroll
            for (int mt = 0; mt < 4; mt++)
                ldsm_x4(af[mt][0], af[mt][1], af[mt][2], af[mt][3],
                        abuf + ((mt * 16 * APITCH + g * 16) << 1));
            #pragma unroll
            for (int np = 0; np < 2; np++) {
                unsigned r0, r1, r2, r3;
                ldsm_x4(r0, r1, r2, r3, bbuf + ((np * 16 * BPITCH + g * 16) << 1));
                bf[2 * np][0] = r0;  bf[2 * np][1] = r1;
                bf[2 * np + 1][0] = r2;  bf[2 * np + 1][1] = r3;
            }
            #pragma unroll
            for (int mt = 0; mt < 4; mt++)
                #pragma unroll
                for (int nt = 0; nt < 4; nt++)
                    mma_f16(acc[mt][nt], af[mt][0], af[mt][1], af[mt][2], af[mt][3],
                            bf[nt][0], bf[nt][1]);
        }
    }

    #pragma unroll
    for (int mt = 0; mt < 4; mt++) {
        #pragma unroll
        for (int i2 = 0; i2 < 2; i2++) {
            int m = m0 + wm + mt * 16 + r + i2 * 8;
            if (m >= M) continue;
            #pragma unroll
            for (int nt = 0; nt < 4; nt++) {
                int n = n0 + wn + nt * 8 + kc * 2;
                float v0 = acc[mt][nt][i2 * 2 + 0];
                float v1 = acc[mt][nt][i2 * 2 + 1];
                if (bias) { v0 += bias[n]; v1 += bias[n + 1]; }
                if (n < nsplit) {
                    __half2 h = __floats2half2_rn(v0, v1);
                    *(__half2*)(C1h + (size_t)m * ld1 + n) = h;
                } else {
                    *(float2*)(C2 + (size_t)m * ld2 + n - nsplit) = make_float2(v0, v1);
                }
            }
        }
    }
}

// ---------------- fused SpMM + residual epilogue (layer 1: fp16 out) ----------------
__global__ void k_spmm_out96(const __half* __restrict__ feat, const int* __restrict__ rowptr,
                             const int* __restrict__ col, const float* __restrict__ rs_src,
                             const float* __restrict__ raw, const float* __restrict__ rs_in,
                             const float* __restrict__ b1, const float* __restrict__ b2,
                             __half* __restrict__ out, int n_rows) {
    int w = (blockIdx.x * blockDim.x + threadIdx.x) >> 5;
    int lane = threadIdx.x & 31;
    if (w >= n_rows) return;
    int s = rowptr[w], e = rowptr[w + 1];
    bool act = lane < 24;
    int d = lane * 4;
    float4 a0 = make_float4(0.f, 0.f, 0.f, 0.f);
    float4 a1 = make_float4(0.f, 0.f, 0.f, 0.f);
    int i = s;
    for (; i + 3 < e; i += 4) {
        int c0 = col[i], c1 = col[i + 1], c2 = col[i + 2], c3 = col[i + 3];
        float s0 = rs_src[c0], s1 = rs_src[c1], s2 = rs_src[c2], s3 = rs_src[c3];
        if (act) {
            uint2 q0 = *(const uint2*)(feat + (size_t)c0 * 96 + d);
            uint2 q1 = *(const uint2*)(feat + (size_t)c1 * 96 + d);
            uint2 q2 = *(const uint2*)(feat + (size_t)c2 * 96 + d);
            uint2 q3 = *(const uint2*)(feat + (size_t)c3 * 96 + d);
            float2 f;
            f = __half22float2(*(__half2*)&q0.x); a0.x += f.x * s0; a0.y += f.y * s0;
            f = __half22float2(*(__half2*)&q0.y); a0.z += f.x * s0; a0.w += f.y * s0;
            f = __half22float2(*(__half2*)&q1.x); a1.x += f.x * s1; a1.y += f.y * s1;
            f = __half22float2(*(__half2*)&q1.y); a1.z += f.x * s1; a1.w += f.y * s1;
            f = __half22float2(*(__half2*)&q2.x); a0.x += f.x * s2; a0.y += f.y * s2;
            f = __half22float2(*(__half2*)&q2.y); a0.z += f.x * s2; a0.w += f.y * s2;
            f = __half22float2(*(__half2*)&q3.x); a1.x += f.x * s3; a1.y += f.y * s3;
            f = __half22float2(*(__half2*)&q3.y); a1.z += f.x * s3; a1.w += f.y * s3;
        }
    }
    for (; i < e; i++) {
        int c0 = col[i];
        float s0 = rs_src[c0];
        if (act) {
            uint2 q0 = *(const uint2*)(feat + (size_t)c0 * 96 + d);
            float2 f;
            f = __half22float2(*(__half2*)&q0.x); a0.x += f.x * s0; a0.y += f.y * s0;
            f = __half22float2(*(__half2*)&q0.y); a0.z += f.x * s0; a0.w += f.y * s0;
        }
    }
    if (act) {
        float sc = rs_in[w];
        float4 r4 = *(const float4*)(raw + (size_t)w * 96 + d);
        float ox = fmaxf(r4.x + b1[d + 0] + b2[d + 0] + (a0.x + a1.x) * sc, 0.f);
        float oy = fmaxf(r4.y + b1[d + 1] + b2[d + 1] + (a0.y + a1.y) * sc, 0.f);
        float oz = fmaxf(r4.z + b1[d + 2] + b2[d + 2] + (a0.z + a1.z) * sc, 0.f);
        float ow = fmaxf(r4.w + b1[d + 3] + b2[d + 3] + (a0.w + a1.w) * sc, 0.f);
        union { __half2 h[2]; uint2 q; } cv;
        cv.h[0] = __floats2half2_rn(ox, oy);
        cv.h[1] = __floats2half2_rn(oz, ow);
        *(uint2*)(out + (size_t)w * 96 + d) = cv.q;
    }
}

// layer 2 (D=64): HALF-WARP per row (16 lanes), fp32 out + fused inverse-norm
__global__ void k_spmm_out64_norm(const __half* __restrict__ feat, const int* __restrict__ rowptr,
                                  const int* __restrict__ col, const float* __restrict__ rs_src,
                                  const float* __restrict__ raw, const float* __restrict__ rs_in,
                                  const float* __restrict__ b1, const float* __restrict__ b2,
                                  float* __restrict__ out, float* __restrict__ invn, int n_rows) {
    int gt = blockIdx.x * blockDim.x + threadIdx.x;
    int w = gt >> 4;
    int lane = threadIdx.x & 15;
    if (w >= n_rows) return;
    int s = rowptr[w], e = rowptr[w + 1];
    int d = lane * 4;
    float4 a0 = make_float4(0.f, 0.f, 0.f, 0.f);
    float4 a1 = make_float4(0.f, 0.f, 0.f, 0.f);
    int i = s;
    for (; i + 3 < e; i += 4) {
        int c0 = col[i], c1 = col[i + 1], c2 = col[i + 2], c3 = col[i + 3];
        float s0 = rs_src[c0], s1 = rs_src[c1], s2 = rs_src[c2], s3 = rs_src[c3];
        uint2 q0 = *(const uint2*)(feat + (size_t)c0 * 64 + d);
        uint2 q1 = *(const uint2*)(feat + (size_t)c1 * 64 + d);
        uint2 q2 = *(const uint2*)(feat + (size_t)c2 * 64 + d);
        uint2 q3 = *(const uint2*)(feat + (size_t)c3 * 64 + d);
        float2 f;
        f = __half22float2(*(__half2*)&q0.x); a0.x += f.x * s0; a0.y += f.y * s0;
        f = __half22float2(*(__half2*)&q0.y); a0.z += f.x * s0; a0.w += f.y * s0;
        f = __half22float2(*(__half2*)&q1.x); a1.x += f.x * s1; a1.y += f.y * s1;
        f = __half22float2(*(__half2*)&q1.y); a1.z += f.x * s1; a1.w += f.y * s1;
        f = __half22float2(*(__half2*)&q2.x); a0.x += f.x * s2; a0.y += f.y * s2;
        f = __half22float2(*(__half2*)&q2.y); a0.z += f.x * s2; a0.w += f.y * s2;
        f = __half22float2(*(__half2*)&q3.x); a1.x += f.x * s3; a1.y += f.y * s3;
        f = __half22float2(*(__half2*)&q3.y); a1.z += f.x * s3; a1.w += f.y * s3;
    }
    for (; i < e; i++) {
        int c0 = col[i];
        float s0 = rs_src[c0];
        uint2 q0 = *(const uint2*)(feat + (size_t)c0 * 64 + d);
        float2 f;
        f = __half22float2(*(__half2*)&q0.x); a0.x += f.x * s0; a0.y += f.y * s0;
        f = __half22float2(*(__half2*)&q0.y); a0.z += f.x * s0; a0.w += f.y * s0;
    }
    float sq;
    {
        float sc = rs_in[w];
        float4 r4 = *(const float4*)(raw + (size_t)w * 64 + d);
        float4 o;
        o.x = fmaxf(r4.x + b1[d + 0] + b2[d + 0] + (a0.x + a1.x) * sc, 0.f);
        o.y = fmaxf(r4.y + b1[d + 1] + b2[d + 1] + (a0.y + a1.y) * sc, 0.f);
        o.z = fmaxf(r4.z + b1[d + 2] + b2[d + 2] + (a0.z + a1.z) * sc, 0.f);
        o.w = fmaxf(r4.w + b1[d + 3] + b2[d + 3] + (a0.w + a1.w) * sc, 0.f);
        *(float4*)(out + (size_t)w * 64 + d) = o;
        sq = o.x * o.x + o.y * o.y + o.z * o.z + o.w * o.w;
    }
    #pragma unroll
    for (int off = 8; off; off >>= 1) sq += __shfl_xor_sync(0xffffffffu, sq, off);
    if (lane == 0) invn[w] = 1.0f / fmaxf(sqrtf(sq), 1e-12f);
}

// ---------------- score: half-warp per pair, float4 loads ----------------
__global__ void k_score_all(const float* __restrict__ hu, const float* __restrict__ hr,
                            const float* __restrict__ invn_u, const float* __restrict__ invn_r,
                            const int* __restrict__ pos_u, const int* __restrict__ pos_r,
                            const int* __restrict__ neg_u, const int* __restrict__ neg_r,
                            float* __restrict__ out) {
    int gt = blockIdx.x * blockDim.x + threadIdx.x;
    int w = gt >> 4;
    int lane = threadIdx.x & 15;
    if (w >= 2 * NEP) return;
    int u, r;
    if (w < NEP) { u = pos_u[w]; r = pos_r[w]; }
    else         { u = neg_u[w - NEP]; r = neg_r[w - NEP]; }
    float4 a4 = *(const float4*)(hu + (size_t)u * D_OUT + lane * 4);
    float4 b4 = *(const float4*)(hr + (size_t)r * D_OUT + lane * 4);
    float s = a4.x * b4.x + a4.y * b4.y + a4.z * b4.z + a4.w * b4.w;
    #pragma unroll
    for (int off = 8; off; off >>= 1) s += __shfl_xor_sync(0xffffffffu, s, off);
    if (lane == 0) out[w] = s * invn_u[u] * invn_r[r];
}

// ---------------- host ----------------
static inline void* sym(const void* s) {
    void* p = nullptr;
    cudaGetSymbolAddress(&p, s);
    return p;
}

extern "C" void kernel_launch(void* const* d_in, const int* in_sizes, int n_in,
                              void* d_out, int out_size) {
    const float* user_feat = (const float*)d_in[0];
    const float* repo_feat = (const float*)d_in[1];
    const float* W_ue = (const float*)d_in[2];   const float* b_ue = (const float*)d_in[3];
    const float* W_re = (const float*)d_in[4];   const float* b_re = (const float*)d_in[5];
    const float* W_hid_ur = (const float*)d_in[6];  const float* b_hid_ur = (const float*)d_in[7];
    const float* W_hid_ru = (const float*)d_in[8];  const float* b_hid_ru = (const float*)d_in[9];
    const float* W_out_ur = (const float*)d_in[10]; const float* b_out_ur = (const float*)d_in[11];
    const float* W_out_ru = (const float*)d_in[12]; const float* b_out_ru = (const float*)d_in[13];
    const float* W_hcu = (const float*)d_in[14]; const float* b_hcu = (const float*)d_in[15];
    const float* W_hcr = (const float*)d_in[16]; const float* b_hcr = (const float*)d_in[17];
    const float* W_ocu = (const float*)d_in[18]; const float* b_ocu = (const float*)d_in[19];
    const float* W_ocr = (const float*)d_in[20]; const float* b_ocr = (const float*)d_in[21];
    const int* e_ur_src = (const int*)d_in[22];
    const int* e_ur_dst = (const int*)d_in[23];
    const int* e_ru_src = (const int*)d_in[24];
    const int* e_ru_dst = (const int*)d_in[25];
    const int* pos_u = (const int*)d_in[26];
    const int* pos_r = (const int*)d_in[27];
    const int* neg_u = (const int*)d_in[28];
    const int* neg_r = (const int*)d_in[29];
    float* out = (float*)d_out;

    __half* a_user = (__half*)sym(g_a_user);
    __half* a_repo = (__half*)sym(g_a_repo);
    __half* feat_u = (__half*)sym(g_feat_u);
    __half* feat_r = (__half*)sym(g_feat_r);
    float*  raw_u  = (float*)sym(g_raw_u);
    float*  raw_r  = (float*)sym(g_raw_r);
    __half* out_user = (__half*)sym(g_out_user);
    __half* out_repo = (__half*)sym(g_out_repo);
    float*  new_user = (float*)sym(g_new_user);
    float*  new_repo = (float*)sym(g_new_repo);
    int* cnt_u_out = (int*)sym(g_cnt_u_out);
    int* cnt_u_in  = (int*)sym(g_cnt_u_in);
    int* cnt_r_out = (int*)sym(g_cnt_r_out);
    int* cnt_r_in  = (int*)sym(g_cnt_r_in);
    float* rs_u_out = (float*)sym(g_rs_u_out);
    float* rs_u_in  = (float*)sym(g_rs_u_in);
    float* rs_r_out = (float*)sym(g_rs_r_out);
    float* rs_r_in  = (float*)sym(g_rs_r_in);
    int* rowptr_ur = (int*)sym(g_rowptr_ur);
    int* rowptr_ru = (int*)sym(g_rowptr_ru);
    int* cursor_ur = (int*)sym(g_cursor_ur);
    int* cursor_ru = (int*)sym(g_cursor_ru);
    int* col_ur = (int*)sym(g_col_ur);
    int* col_ru = (int*)sym(g_col_ru);
    int* part   = (int*)sym(g_part);
    float* invn_u = (float*)sym(g_invn_u);
    float* invn_r = (float*)sym(g_invn_r);
    __half* WCt_u1 = (__half*)sym(g_WCt_u1);
    __half* WCt_r1 = (__half*)sym(g_WCt_r1);
    float* bc_u1 = (float*)sym(g_bc_u1);
    float* bc_r1 = (float*)sym(g_bc_r1);
    __half* wc2t_u = (__half*)sym(g_wc2t_u);
    __half* wc2t_r = (__half*)sym(g_wc2t_r);

    const int T = 256;
    auto blocks = [](long n, int t) { return (int)((n + t - 1) / t); };

    // one-time stream/event creation (host resources only; no device memory)
    static cudaStream_t s_pre = nullptr;
    static cudaEvent_t ev_fork = nullptr, ev_pre = nullptr;
    if (s_pre == nullptr) {
        cudaStreamCreateWithFlags(&s_pre, cudaStreamNonBlocking);
        cudaEventCreateWithFlags(&ev_fork, cudaEventDisableTiming);
        cudaEventCreateWithFlags(&ev_pre, cudaEventDisableTiming);
    }

    // ---- fork: graph-structure pipeline on s_pre ----
    cudaEventRecord(ev_fork, 0);
    cudaStreamWaitEvent(s_pre, ev_fork, 0);

    cudaMemsetAsync(cnt_u_out, 0, N_USER * sizeof(int), s_pre);
    cudaMemsetAsync(cnt_u_in,  0, N_USER * sizeof(int), s_pre);
    cudaMemsetAsync(cnt_r_out, 0, N_REPO * sizeof(int), s_pre);
    cudaMemsetAsync(cnt_r_in,  0, N_REPO * sizeof(int), s_pre);
    k_count_all<<<blocks(2L * NE, T), T, 0, s_pre>>>(e_ur_src, e_ur_dst, e_ru_src, e_ru_dst);
    k_rsqrt_all<<<blocks(2L * (N_USER + N_REPO), T), T, 0, s_pre>>>();
    int nb_r = (N_REPO + 1023) / 1024;
    int nb_u = (N_USER + 1023) / 1024;
    k_scan_block<<<nb_r, 1024, 0, s_pre>>>(cnt_r_in, rowptr_ur, part, N_REPO);
    k_scan_part<<<1, 128, 0, s_pre>>>(part, nb_r);
    k_scan_add<<<blocks(N_REPO, T), T, 0, s_pre>>>(rowptr_ur, cursor_ur, part, N_REPO);
    k_scan_block<<<nb_u, 1024, 0, s_pre>>>(cnt_u_in, rowptr_ru, part, N_USER);
    k_scan_part<<<1, 128, 0, s_pre>>>(part, nb_u);
    k_scan_add<<<blocks(N_USER, T), T, 0, s_pre>>>(rowptr_ru, cursor_ru, part, N_USER);
    k_fill_all<<<blocks(2L * NE, T), T, 0, s_pre>>>(e_ur_src, e_ur_dst, e_ru_src, e_ru_dst);
    cudaEventRecord(ev_pre, s_pre);

    // ---- main stream: conversion + weight prep + layer-1 GEMMs ----
    k_tofp16<<<blocks((long)NU8 + NR8, T), T>>>(user_feat, repo_feat);
    k_fold<<<blocks(FOLD_TOTAL, T), T>>>(W_ue, b_ue, W_hid_ur, W_hcu,
                                         W_re, b_re, W_hid_ru, W_hcr,
                                         W_out_ur, W_ocu, W_out_ru, W_ocr);

    dim3 tb(128);
    auto grid = [](int M, int N) { return dim3(N / BN, (M + BM - 1) / BM); };

    k_gemm_f16<<<grid(N_REPO, 192), tb>>>(a_repo, WCt_r1,
        feat_r, D_HID, raw_r, D_HID, D_HID, N_REPO, 192, D_IN, bc_r1);
    k_gemm_f16<<<grid(N_USER, 192), tb>>>(a_user, WCt_u1,
        feat_u, D_HID, raw_u, D_HID, D_HID, N_USER, 192, D_IN, bc_u1);

    // ---- join: SpMM needs CSR + rs + GEMM outputs ----
    cudaStreamWaitEvent(0, ev_pre, 0);

    // layer-1 SpMM + residual -> fp16 out
    k_spmm_out96<<<blocks(N_USER * 32L, T), T>>>(feat_r, rowptr_ru, col_ru, rs_r_out,
                                                 raw_u, rs_u_in, b_hcu, b_hid_ru,
                                                 out_user, N_USER);
    k_spmm_out96<<<blocks(N_REPO * 32L, T), T>>>(feat_u, rowptr_ur, col_ur, rs_u_out,
                                                 raw_r, rs_r_in, b_hcr, b_hid_ur,
                                                 out_repo, N_REPO);

    // layer-2 GEMMs (K=96)
    k_gemm_f16<<<grid(N_REPO, 128), tb>>>(out_repo, wc2t_r,
        feat_r, D_OUT, raw_r, D_OUT, D_OUT, N_REPO, 128, D_HID, nullptr);
    k_gemm_f16<<<grid(N_USER, 128), tb>>>(out_user, wc2t_u,
        feat_u, D_OUT, raw_u, D_OUT, D_OUT, N_USER, 128, D_HID, nullptr);

    // layer-2 SpMM + residual + norm (half-warp per row)
    k_spmm_out64_norm<<<blocks(N_USER * 16L, T), T>>>(feat_r, rowptr_ru, col_ru, rs_r_out,
                                                      raw_u, rs_u_in, b_ocu, b_out_ru,
                                                      new_user, invn_u, N_USER);
    k_spmm_out64_norm<<<blocks(N_REPO * 16L, T), T>>>(feat_u, rowptr_ur, col_ur, rs_u_out,
                                                      raw_r, rs_r_in, b_ocr, b_out_ur,
                                                      new_repo, invn_r, N_REPO);

    // cosine scores (half-warp per pair)
    k_score_all<<<blocks(2L * NEP * 16, T), T>>>(new_user, new_repo, invn_u, invn_r,
                                                 pos_u, pos_r, neg_u, neg_r, out);
}